// round 1
// baseline (speedup 1.0000x reference)
#include <cuda_runtime.h>

// Problem constants
#define Tt   8192      // B*S tokens
#define Dd   1024      // model dim
#define Ff   4096      // ffn dim
#define Oo   1024      // output dim
#define Ee   4         // routed experts
#define NSs  2         // shared experts
#define NEXP 6         // total expert slots (2 shared + 4 routed)
#define N1   24576     // NEXP * Ff

// GEMM tiling
#define BM 128
#define BN 128
#define BK 8
#define TM 8
#define TN 8

// Scratch (device globals: allocation-free)
__device__ float g_H[(size_t)Tt * N1];   // hidden activations, pre-scaled by gate coef
__device__ float g_m[Tt * Ee];           // routed gate weights (0 if not in top-2)

// ---------------------------------------------------------------------------
// Gating: logits = x @ gate_w + gate_b ; softmax ; top-2 weights (not renorm'd)
// One warp per token.
// ---------------------------------------------------------------------------
__global__ void gate_kernel(const float* __restrict__ x,
                            const float* __restrict__ gw,
                            const float* __restrict__ gb) {
    int t    = blockIdx.x * (blockDim.x >> 5) + (threadIdx.x >> 5);
    int lane = threadIdx.x & 31;
    if (t >= Tt) return;

    float acc0 = 0.f, acc1 = 0.f, acc2 = 0.f, acc3 = 0.f;
    const float* xr = x + (size_t)t * Dd;
    for (int d = lane; d < Dd; d += 32) {
        float xv = xr[d];
        acc0 += xv * gw[d * Ee + 0];
        acc1 += xv * gw[d * Ee + 1];
        acc2 += xv * gw[d * Ee + 2];
        acc3 += xv * gw[d * Ee + 3];
    }
    #pragma unroll
    for (int off = 16; off; off >>= 1) {
        acc0 += __shfl_xor_sync(0xffffffffu, acc0, off);
        acc1 += __shfl_xor_sync(0xffffffffu, acc1, off);
        acc2 += __shfl_xor_sync(0xffffffffu, acc2, off);
        acc3 += __shfl_xor_sync(0xffffffffu, acc3, off);
    }
    if (lane == 0) {
        float lg[Ee] = {acc0 + gb[0], acc1 + gb[1], acc2 + gb[2], acc3 + gb[3]};
        float mx = lg[0];
        #pragma unroll
        for (int e = 1; e < Ee; e++) mx = fmaxf(mx, lg[e]);
        float w[Ee]; float s = 0.f;
        #pragma unroll
        for (int e = 0; e < Ee; e++) { w[e] = __expf(lg[e] - mx); s += w[e]; }
        float inv = 1.f / s;
        #pragma unroll
        for (int e = 0; e < Ee; e++) w[e] *= inv;

        // top-2 (ties -> lowest index, matching jax.lax.top_k)
        int i1 = 0;
        #pragma unroll
        for (int e = 1; e < Ee; e++) if (w[e] > w[i1]) i1 = e;
        int i2 = -1;
        #pragma unroll
        for (int e = 0; e < Ee; e++) {
            if (e == i1) continue;
            if (i2 < 0 || w[e] > w[i2]) i2 = e;
        }
        #pragma unroll
        for (int e = 0; e < Ee; e++) {
            float v = (e == i1 || e == i2) ? w[e] : 0.f;
            g_m[t * Ee + e] = v;
        }
    }
}

// ---------------------------------------------------------------------------
// GEMM1: H[t, j*F+f] = coef(t,j) * relu( x[t,:] @ W1_j[:,f] + b1_j[f] )
// A = x [Tt x Dd] row-major, B = W1_j [Dd x Ff] row-major (per slot).
// Slot j is constant per 128-wide N tile (Ff % BN == 0).
// ---------------------------------------------------------------------------
__global__ __launch_bounds__(256)
void gemm1_kernel(const float* __restrict__ x,
                  const float* __restrict__ sw1, const float* __restrict__ sb1,
                  const float* __restrict__ rw1, const float* __restrict__ rb1) {
    __shared__ float As[BK][BM];
    __shared__ float Bs[BK][BN];

    const int bn = blockIdx.x;
    const int bm = blockIdx.y;
    const int tid = threadIdx.x;

    const int n0 = bn * BN;
    const int j  = n0 / Ff;           // expert slot (const per block)
    const int f0 = n0 - j * Ff;

    const float* Wb = (j < NSs) ? (sw1 + (size_t)j * Dd * Ff)
                                : (rw1 + (size_t)(j - NSs) * Dd * Ff);
    const float* bb = (j < NSs) ? (sb1 + j * Ff) : (rb1 + (j - NSs) * Ff);

    const int arow = tid >> 1;            // 0..127
    const int acol = (tid & 1) * 4;       // 0 or 4
    const int brow = tid >> 5;            // 0..7
    const int bcol = (tid & 31) * 4;      // 0..124

    const int tx = tid & 15, ty = tid >> 4;

    float acc[TM][TN];
    #pragma unroll
    for (int i = 0; i < TM; i++)
        #pragma unroll
        for (int jj = 0; jj < TN; jj++) acc[i][jj] = 0.f;

    const float* Aptr = x + (size_t)(bm * BM + arow) * Dd + acol;
    const float* Bptr = Wb + (size_t)brow * Ff + f0 + bcol;

    for (int k0 = 0; k0 < Dd; k0 += BK) {
        float4 av = *(const float4*)(Aptr + k0);
        As[acol + 0][arow] = av.x;
        As[acol + 1][arow] = av.y;
        As[acol + 2][arow] = av.z;
        As[acol + 3][arow] = av.w;
        float4 bv = *(const float4*)(Bptr + (size_t)k0 * Ff);
        *(float4*)&Bs[brow][bcol] = bv;
        __syncthreads();

        #pragma unroll
        for (int k = 0; k < BK; k++) {
            float4 a0 = *(const float4*)&As[k][ty * TM];
            float4 a1 = *(const float4*)&As[k][ty * TM + 4];
            float4 b0 = *(const float4*)&Bs[k][tx * TN];
            float4 b1 = *(const float4*)&Bs[k][tx * TN + 4];
            float a[TM] = {a0.x, a0.y, a0.z, a0.w, a1.x, a1.y, a1.z, a1.w};
            float b[TN] = {b0.x, b0.y, b0.z, b0.w, b1.x, b1.y, b1.z, b1.w};
            #pragma unroll
            for (int i = 0; i < TM; i++)
                #pragma unroll
                for (int jj = 0; jj < TN; jj++)
                    acc[i][jj] += a[i] * b[jj];
        }
        __syncthreads();
    }

    // epilogue: bias + relu + gate scale, write H
    const int rowbase = bm * BM + ty * TM;
    const int colbase = n0 + tx * TN;
    #pragma unroll
    for (int i = 0; i < TM; i++) {
        const int gr = rowbase + i;
        const float coef = (j < NSs) ? (1.0f / NSs) : g_m[gr * Ee + (j - NSs)];
        float* Hrow = g_H + (size_t)gr * N1 + colbase;
        #pragma unroll
        for (int jj = 0; jj < TN; jj++) {
            const int f = f0 + tx * TN + jj;
            float v = fmaxf(acc[i][jj] + bb[f], 0.f) * coef;
            Hrow[jj] = v;
        }
    }
}

// ---------------------------------------------------------------------------
// GEMM2: out[t,o] = H[t,:] @ W2_cat[:,o] + 0.5*(sb2[0,o]+sb2[1,o])
//                   + sum_e m[t,e] * rb2[e,o]
// A = g_H [Tt x N1], B row k -> slot j=k/Ff, f=k%Ff, W2_j[f, o].
// ---------------------------------------------------------------------------
__global__ __launch_bounds__(256)
void gemm2_kernel(const float* __restrict__ sw2, const float* __restrict__ sb2,
                  const float* __restrict__ rw2, const float* __restrict__ rb2,
                  float* __restrict__ out) {
    __shared__ float As[BK][BM];
    __shared__ float Bs[BK][BN];

    const int bn = blockIdx.x;
    const int bm = blockIdx.y;
    const int tid = threadIdx.x;
    const int n0 = bn * BN;

    const int arow = tid >> 1;
    const int acol = (tid & 1) * 4;
    const int brow = tid >> 5;
    const int bcol = (tid & 31) * 4;
    const int tx = tid & 15, ty = tid >> 4;

    float acc[TM][TN];
    #pragma unroll
    for (int i = 0; i < TM; i++)
        #pragma unroll
        for (int jj = 0; jj < TN; jj++) acc[i][jj] = 0.f;

    const float* Aptr = g_H + (size_t)(bm * BM + arow) * N1 + acol;

    for (int k0 = 0; k0 < N1; k0 += BK) {
        float4 av = *(const float4*)(Aptr + k0);
        As[acol + 0][arow] = av.x;
        As[acol + 1][arow] = av.y;
        As[acol + 2][arow] = av.z;
        As[acol + 3][arow] = av.w;

        const int k = k0 + brow;
        const int j = k >> 12;            // k / Ff
        const int f = k & (Ff - 1);       // k % Ff
        const float* w2row = (j < NSs)
            ? (sw2 + ((size_t)j * Ff + f) * Oo)
            : (rw2 + ((size_t)(j - NSs) * Ff + f) * Oo);
        float4 bv = *(const float4*)(w2row + n0 + bcol);
        *(float4*)&Bs[brow][bcol] = bv;
        __syncthreads();

        #pragma unroll
        for (int kk = 0; kk < BK; kk++) {
            float4 a0 = *(const float4*)&As[kk][ty * TM];
            float4 a1 = *(const float4*)&As[kk][ty * TM + 4];
            float4 b0 = *(const float4*)&Bs[kk][tx * TN];
            float4 b1 = *(const float4*)&Bs[kk][tx * TN + 4];
            float a[TM] = {a0.x, a0.y, a0.z, a0.w, a1.x, a1.y, a1.z, a1.w};
            float b[TN] = {b0.x, b0.y, b0.z, b0.w, b1.x, b1.y, b1.z, b1.w};
            #pragma unroll
            for (int i = 0; i < TM; i++)
                #pragma unroll
                for (int jj = 0; jj < TN; jj++)
                    acc[i][jj] += a[i] * b[jj];
        }
        __syncthreads();
    }

    const int rowbase = bm * BM + ty * TM;
    const int colbase = n0 + tx * TN;
    #pragma unroll
    for (int i = 0; i < TM; i++) {
        const int gr = rowbase + i;
        float me[Ee];
        #pragma unroll
        for (int e = 0; e < Ee; e++) me[e] = g_m[gr * Ee + e];
        float* orow = out + (size_t)gr * Oo + colbase;
        #pragma unroll
        for (int jj = 0; jj < TN; jj++) {
            const int gc = colbase + jj;
            float v = acc[i][jj] + 0.5f * (sb2[gc] + sb2[Oo + gc]);
            #pragma unroll
            for (int e = 0; e < Ee; e++) v += me[e] * rb2[e * Oo + gc];
            orow[jj] = v;
        }
    }
}

// ---------------------------------------------------------------------------
extern "C" void kernel_launch(void* const* d_in, const int* in_sizes, int n_in,
                              void* d_out, int out_size) {
    const float* x      = (const float*)d_in[0];
    const float* gate_w = (const float*)d_in[1];
    const float* gate_b = (const float*)d_in[2];
    const float* sw1    = (const float*)d_in[3];
    const float* sb1    = (const float*)d_in[4];
    const float* sw2    = (const float*)d_in[5];
    const float* sb2    = (const float*)d_in[6];
    const float* rw1    = (const float*)d_in[7];
    const float* rb1    = (const float*)d_in[8];
    const float* rw2    = (const float*)d_in[9];
    const float* rb2    = (const float*)d_in[10];
    float* out = (float*)d_out;

    gate_kernel<<<Tt / 8, 256>>>(x, gate_w, gate_b);

    dim3 g1(N1 / BN, Tt / BM);   // 192 x 64
    gemm1_kernel<<<g1, 256>>>(x, sw1, sb1, rw1, rb1);

    dim3 g2(Oo / BN, Tt / BM);   // 8 x 64
    gemm2_kernel<<<g2, 256>>>(sw2, sb2, rw2, rb2, out);
}

// round 3
// speedup vs baseline: 3.3472x; 3.3472x over previous
#include <cuda_runtime.h>
#include <cuda_bf16.h>
#include <stdint.h>

#define Tt 8192
#define Dd 1024
#define Ff 4096
#define Oo 1024
#define Ee 4
#define NSs 2
#define N1 24576

#define BM 128
#define BN 128
#define BKC 64                        // K elems per chunk (bf16) -> 128B rows
#define STAGES 3
#define TILEB (128 * 128)             // bytes per smem tile
#define STAGEB (4 * TILEB)            // Ah, Al, Bh, Bl
#define SMEM_DYN (STAGES * STAGEB)    // 196608 B

// ---------------- device scratch (allocation-free) ----------------
__device__ __align__(256) __nv_bfloat16 g_Xh[(size_t)Tt * Dd];
__device__ __align__(256) __nv_bfloat16 g_Xl[(size_t)Tt * Dd];
__device__ __align__(256) __nv_bfloat16 g_W1h[(size_t)N1 * Dd];   // [n][k]
__device__ __align__(256) __nv_bfloat16 g_W1l[(size_t)N1 * Dd];
__device__ __align__(256) __nv_bfloat16 g_W2h[(size_t)Oo * N1];   // [o][jf]
__device__ __align__(256) __nv_bfloat16 g_W2l[(size_t)Oo * N1];
__device__ __align__(256) __nv_bfloat16 g_Hh[(size_t)Tt * N1];
__device__ __align__(256) __nv_bfloat16 g_Hl[(size_t)Tt * N1];
__device__ float g_m[Tt * Ee];

// ---------------- helpers ----------------
__device__ __forceinline__ uint32_t smem_u32(const void* p) {
    return (uint32_t)__cvta_generic_to_shared(p);
}
__device__ __forceinline__ uint32_t sw128(uint32_t x) { return x ^ ((x >> 3) & 0x70u); }

__device__ __forceinline__ void cp16(uint32_t s, const void* g) {
    asm volatile("cp.async.cg.shared.global [%0], [%1], 16;\n" :: "r"(s), "l"(g));
}
__device__ __forceinline__ void cp_commit() { asm volatile("cp.async.commit_group;\n"); }
template <int N> __device__ __forceinline__ void cp_wait() {
    asm volatile("cp.async.wait_group %0;\n" :: "n"(N));
}

__device__ __forceinline__ void ldsm_x4(uint32_t* r, uint32_t addr) {
    asm volatile("ldmatrix.sync.aligned.m8n8.x4.shared.b16 {%0,%1,%2,%3}, [%4];"
                 : "=r"(r[0]), "=r"(r[1]), "=r"(r[2]), "=r"(r[3]) : "r"(addr));
}
__device__ __forceinline__ void mma16816(float* d, const uint32_t* a, const uint32_t* b) {
    asm volatile(
        "mma.sync.aligned.m16n8k16.row.col.f32.bf16.bf16.f32 "
        "{%0,%1,%2,%3}, {%4,%5,%6,%7}, {%8,%9}, {%0,%1,%2,%3};"
        : "+f"(d[0]), "+f"(d[1]), "+f"(d[2]), "+f"(d[3])
        : "r"(a[0]), "r"(a[1]), "r"(a[2]), "r"(a[3]), "r"(b[0]), "r"(b[1]));
}

// ---------------- gating ----------------
__global__ void gate_kernel(const float* __restrict__ x,
                            const float* __restrict__ gw,
                            const float* __restrict__ gb) {
    int t = blockIdx.x * (blockDim.x >> 5) + (threadIdx.x >> 5);
    int lane = threadIdx.x & 31;
    if (t >= Tt) return;
    float a0 = 0.f, a1 = 0.f, a2 = 0.f, a3 = 0.f;
    const float* xr = x + (size_t)t * Dd;
    for (int d = lane; d < Dd; d += 32) {
        float xv = xr[d];
        a0 += xv * gw[d * Ee + 0]; a1 += xv * gw[d * Ee + 1];
        a2 += xv * gw[d * Ee + 2]; a3 += xv * gw[d * Ee + 3];
    }
    #pragma unroll
    for (int off = 16; off; off >>= 1) {
        a0 += __shfl_xor_sync(~0u, a0, off); a1 += __shfl_xor_sync(~0u, a1, off);
        a2 += __shfl_xor_sync(~0u, a2, off); a3 += __shfl_xor_sync(~0u, a3, off);
    }
    if (lane == 0) {
        float lg[Ee] = {a0 + gb[0], a1 + gb[1], a2 + gb[2], a3 + gb[3]};
        float mx = fmaxf(fmaxf(lg[0], lg[1]), fmaxf(lg[2], lg[3]));
        float w[Ee]; float s = 0.f;
        #pragma unroll
        for (int e = 0; e < Ee; e++) { w[e] = __expf(lg[e] - mx); s += w[e]; }
        float inv = 1.f / s;
        #pragma unroll
        for (int e = 0; e < Ee; e++) w[e] *= inv;
        int i1 = 0;
        #pragma unroll
        for (int e = 1; e < Ee; e++) if (w[e] > w[i1]) i1 = e;
        int i2 = -1;
        #pragma unroll
        for (int e = 0; e < Ee; e++) {
            if (e == i1) continue;
            if (i2 < 0 || w[e] > w[i2]) i2 = e;
        }
        #pragma unroll
        for (int e = 0; e < Ee; e++)
            g_m[t * Ee + e] = (e == i1 || e == i2) ? w[e] : 0.f;
    }
}

// ---------------- conversions ----------------
__global__ void cvt_x(const float* __restrict__ x) {
    int i = blockIdx.x * blockDim.x + threadIdx.x;
    float v = x[i];
    __nv_bfloat16 h = __float2bfloat16(v);
    g_Xh[i] = h;
    g_Xl[i] = __float2bfloat16(v - __bfloat162float(h));
}

__global__ void cvt_w1(const float* __restrict__ sw1, const float* __restrict__ rw1) {
    __shared__ float t[32][33];
    int nb = blockIdx.x * 32, kb = blockIdx.y * 32;
    int j = nb >> 12, f0 = nb & (Ff - 1);
    const float* W = (j < NSs) ? sw1 + (size_t)j * Dd * Ff : rw1 + (size_t)(j - NSs) * Dd * Ff;
    for (int i = threadIdx.y; i < 32; i += 8)
        t[i][threadIdx.x] = W[(size_t)(kb + i) * Ff + f0 + threadIdx.x];
    __syncthreads();
    for (int i = threadIdx.y; i < 32; i += 8) {
        int n = nb + i, k = kb + threadIdx.x;
        float v = t[threadIdx.x][i];
        __nv_bfloat16 h = __float2bfloat16(v);
        g_W1h[(size_t)n * Dd + k] = h;
        g_W1l[(size_t)n * Dd + k] = __float2bfloat16(v - __bfloat162float(h));
    }
}

__global__ void cvt_w2(const float* __restrict__ sw2, const float* __restrict__ rw2) {
    __shared__ float t[32][33];
    int ob = blockIdx.x * 32, cb = blockIdx.y * 32;
    int j = cb >> 12, f0 = cb & (Ff - 1);
    const float* W = (j < NSs) ? sw2 + (size_t)j * Ff * Oo : rw2 + (size_t)(j - NSs) * Ff * Oo;
    for (int i = threadIdx.y; i < 32; i += 8)
        t[i][threadIdx.x] = W[(size_t)(f0 + i) * Oo + ob + threadIdx.x];
    __syncthreads();
    for (int i = threadIdx.y; i < 32; i += 8) {
        int o = ob + i, c = cb + threadIdx.x;
        float v = t[threadIdx.x][i];
        __nv_bfloat16 h = __float2bfloat16(v);
        g_W2h[(size_t)o * N1 + c] = h;
        g_W2l[(size_t)o * N1 + c] = __float2bfloat16(v - __bfloat162float(h));
    }
}

// ---------------- GEMM machinery ----------------
__device__ __forceinline__ void load_tile256(uint32_t sbase, const __nv_bfloat16* g,
                                             int row0, int k0, int pitch, int tid) {
    int r = tid >> 3;                 // 0..31
    int c16 = (tid & 7) * 16;         // byte col within 128B row
    const char* gp = (const char*)g + ((size_t)(row0 + r) * pitch + k0) * 2 + c16;
    size_t gstep = (size_t)32 * pitch * 2;
    #pragma unroll
    for (int rr = 0; rr < 128; rr += 32) {
        cp16(sbase + sw128((uint32_t)((r + rr) * 128 + c16)), gp);
        gp += gstep;
    }
}

__device__ __forceinline__ void load_stage(uint32_t st,
                                           const __nv_bfloat16* Ah, const __nv_bfloat16* Al,
                                           int pitchA, int m0,
                                           const __nv_bfloat16* Bh, const __nv_bfloat16* Bl,
                                           int pitchB, int n0, int k0, int tid) {
    load_tile256(st + 0 * TILEB, Ah, m0, k0, pitchA, tid);
    load_tile256(st + 1 * TILEB, Al, m0, k0, pitchA, tid);
    load_tile256(st + 2 * TILEB, Bh, n0, k0, pitchB, tid);
    load_tile256(st + 3 * TILEB, Bl, n0, k0, pitchB, tid);
    cp_commit();
}

// acc[mi][ni][4]; warp tile 64x32 (wm in 0..1, wn in 0..3)
__device__ __forceinline__ void mainloop(float acc[4][4][4], uint32_t sb,
                                         const __nv_bfloat16* Ah, const __nv_bfloat16* Al,
                                         int pitchA, int m0,
                                         const __nv_bfloat16* Bh, const __nv_bfloat16* Bl,
                                         int pitchB, int n0, int K) {
    const int tid = threadIdx.x;
    const int wid = tid >> 5, lane = tid & 31;
    const int wm = wid >> 2, wn = wid & 3;
    const int NC = K / BKC;

    #pragma unroll
    for (int mi = 0; mi < 4; mi++)
        #pragma unroll
        for (int ni = 0; ni < 4; ni++)
            #pragma unroll
            for (int d = 0; d < 4; d++) acc[mi][ni][d] = 0.f;

    #pragma unroll
    for (int s = 0; s < STAGES; s++)
        load_stage(sb + s * STAGEB, Ah, Al, pitchA, m0, Bh, Bl, pitchB, n0, s * BKC, tid);

    // per-lane base offsets for ldmatrix
    const uint32_t aRow = (uint32_t)(wm * 64 + (lane & 15));
    const uint32_t aKb  = (uint32_t)(((lane >> 4) & 1) << 4);
    const uint32_t bRow = (uint32_t)(wn * 32 + (lane & 7) + (((lane >> 4) & 1) << 3));
    const uint32_t bKb  = (uint32_t)(((lane >> 3) & 1) << 4);

    for (int c = 0; c < NC; c++) {
        int b = c - (c / STAGES) * STAGES;
        uint32_t st = sb + b * STAGEB;
        int pend = NC - 1 - c; if (pend > STAGES - 1) pend = STAGES - 1;
        if (pend >= 2) cp_wait<2>(); else if (pend == 1) cp_wait<1>(); else cp_wait<0>();
        __syncthreads();

        #pragma unroll
        for (int ks = 0; ks < 4; ks++) {
            const uint32_t kb = (uint32_t)(ks * 32);
            uint32_t af[2][4][4];
            uint32_t bf[2][4][2];
            #pragma unroll
            for (int mi = 0; mi < 4; mi++) {
                uint32_t off = sw128((aRow + mi * 16) * 128 + kb + aKb);
                ldsm_x4(af[0][mi], st + 0 * TILEB + off);
                ldsm_x4(af[1][mi], st + 1 * TILEB + off);
            }
            #pragma unroll
            for (int n2 = 0; n2 < 2; n2++) {
                uint32_t off = sw128((bRow + n2 * 16) * 128 + kb + bKb);
                uint32_t r[4];
                ldsm_x4(r, st + 2 * TILEB + off);
                bf[0][n2 * 2][0] = r[0]; bf[0][n2 * 2][1] = r[1];
                bf[0][n2 * 2 + 1][0] = r[2]; bf[0][n2 * 2 + 1][1] = r[3];
                ldsm_x4(r, st + 3 * TILEB + off);
                bf[1][n2 * 2][0] = r[0]; bf[1][n2 * 2][1] = r[1];
                bf[1][n2 * 2 + 1][0] = r[2]; bf[1][n2 * 2 + 1][1] = r[3];
            }
            #pragma unroll
            for (int mi = 0; mi < 4; mi++)
                #pragma unroll
                for (int ni = 0; ni < 4; ni++) {
                    mma16816(acc[mi][ni], af[0][mi], bf[0][ni]);  // hh
                    mma16816(acc[mi][ni], af[0][mi], bf[1][ni]);  // h*l
                    mma16816(acc[mi][ni], af[1][mi], bf[0][ni]);  // l*h
                }
        }
        __syncthreads();
        if (c + STAGES < NC)
            load_stage(st, Ah, Al, pitchA, m0, Bh, Bl, pitchB, n0, (c + STAGES) * BKC, tid);
    }
}

// ---------------- GEMM1: H = split(coef * relu(X @ W1 + b1)) ----------------
__global__ __launch_bounds__(256, 1)
void gemm1_mma(const float* __restrict__ sb1, const float* __restrict__ rb1) {
    extern __shared__ __align__(1024) char smem[];
    uint32_t sb = smem_u32(smem);
    const int m0 = blockIdx.x * BM;   // m fastest: X stays L2-resident
    const int n0 = blockIdx.y * BN;

    float acc[4][4][4];
    mainloop(acc, sb, g_Xh, g_Xl, Dd, m0, g_W1h, g_W1l, Dd, n0, Dd);

    const int tid = threadIdx.x, wid = tid >> 5, lane = tid & 31;
    const int wm = wid >> 2, wn = wid & 3;
    const int j = n0 >> 12, f0 = n0 & (Ff - 1);
    const float* bb = (j < NSs) ? sb1 + j * Ff : rb1 + (j - NSs) * Ff;

    #pragma unroll
    for (int mi = 0; mi < 4; mi++) {
        #pragma unroll
        for (int h = 0; h < 2; h++) {
            const int row = m0 + wm * 64 + mi * 16 + (lane >> 2) + h * 8;
            const float coef = (j < NSs) ? 0.5f : g_m[row * Ee + (j - NSs)];
            #pragma unroll
            for (int ni = 0; ni < 4; ni++) {
                const int col = wn * 32 + ni * 8 + (lane & 3) * 2;  // within block
                float v0 = fmaxf(acc[mi][ni][h * 2 + 0] + bb[f0 + col], 0.f) * coef;
                float v1 = fmaxf(acc[mi][ni][h * 2 + 1] + bb[f0 + col + 1], 0.f) * coef;
                __nv_bfloat16 h0 = __float2bfloat16(v0);
                __nv_bfloat16 h1 = __float2bfloat16(v1);
                __nv_bfloat162 hv; hv.x = h0; hv.y = h1;
                __nv_bfloat162 lv;
                lv.x = __float2bfloat16(v0 - __bfloat162float(h0));
                lv.y = __float2bfloat16(v1 - __bfloat162float(h1));
                *(__nv_bfloat162*)(g_Hh + (size_t)row * N1 + n0 + col) = hv;
                *(__nv_bfloat162*)(g_Hl + (size_t)row * N1 + n0 + col) = lv;
            }
        }
    }
}

// ---------------- GEMM2: out = H @ W2 + biases ----------------
__global__ __launch_bounds__(256, 1)
void gemm2_mma(const float* __restrict__ sb2, const float* __restrict__ rb2,
               float* __restrict__ out) {
    extern __shared__ __align__(1024) char smem[];
    uint32_t sb = smem_u32(smem);
    const int n0 = blockIdx.x * BN;   // n fastest: blocks share H m-tile in L2
    const int m0 = blockIdx.y * BM;

    float acc[4][4][4];
    mainloop(acc, sb, g_Hh, g_Hl, N1, m0, g_W2h, g_W2l, N1, n0, N1);

    const int tid = threadIdx.x, wid = tid >> 5, lane = tid & 31;
    const int wm = wid >> 2, wn = wid & 3;

    #pragma unroll
    for (int mi = 0; mi < 4; mi++) {
        #pragma unroll
        for (int h = 0; h < 2; h++) {
            const int row = m0 + wm * 64 + mi * 16 + (lane >> 2) + h * 8;
            const float m0e = g_m[row * Ee + 0], m1e = g_m[row * Ee + 1];
            const float m2e = g_m[row * Ee + 2], m3e = g_m[row * Ee + 3];
            #pragma unroll
            for (int ni = 0; ni < 4; ni++) {
                const int col = n0 + wn * 32 + ni * 8 + (lane & 3) * 2;
                float2 v;
                v.x = acc[mi][ni][h * 2 + 0]; v.y = acc[mi][ni][h * 2 + 1];
                v.x += 0.5f * (sb2[col] + sb2[Oo + col]);
                v.y += 0.5f * (sb2[col + 1] + sb2[Oo + col + 1]);
                v.x += m0e * rb2[col] + m1e * rb2[Oo + col]
                     + m2e * rb2[2 * Oo + col] + m3e * rb2[3 * Oo + col];
                v.y += m0e * rb2[col + 1] + m1e * rb2[Oo + col + 1]
                     + m2e * rb2[2 * Oo + col + 1] + m3e * rb2[3 * Oo + col + 1];
                *(float2*)(out + (size_t)row * Oo + col) = v;
            }
        }
    }
}

// ---------------- launch ----------------
extern "C" void kernel_launch(void* const* d_in, const int* in_sizes, int n_in,
                              void* d_out, int out_size) {
    const float* x      = (const float*)d_in[0];
    const float* gate_w = (const float*)d_in[1];
    const float* gate_b = (const float*)d_in[2];
    const float* sw1    = (const float*)d_in[3];
    const float* sb1    = (const float*)d_in[4];
    const float* sw2    = (const float*)d_in[5];
    const float* sb2    = (const float*)d_in[6];
    const float* rw1    = (const float*)d_in[7];
    const float* rb1    = (const float*)d_in[8];
    const float* rw2    = (const float*)d_in[9];
    const float* rb2    = (const float*)d_in[10];
    float* out = (float*)d_out;

    cudaFuncSetAttribute(gemm1_mma, cudaFuncAttributeMaxDynamicSharedMemorySize, SMEM_DYN);
    cudaFuncSetAttribute(gemm2_mma, cudaFuncAttributeMaxDynamicSharedMemorySize, SMEM_DYN);

    gate_kernel<<<Tt / 8, 256>>>(x, gate_w, gate_b);
    cvt_x<<<(Tt * Dd) / 256, 256>>>(x);
    dim3 bt(32, 8);
    cvt_w1<<<dim3(N1 / 32, Dd / 32), bt>>>(sw1, rw1);
    cvt_w2<<<dim3(Oo / 32, N1 / 32), bt>>>(sw2, rw2);

    gemm1_mma<<<dim3(Tt / BM, N1 / BN), 256, SMEM_DYN>>>(sb1, rb1);
    gemm2_mma<<<dim3(Oo / BN, Tt / BM), 256, SMEM_DYN>>>(sb2, rb2, out);
}

// round 4
// speedup vs baseline: 5.0499x; 1.5087x over previous
#include <cuda_runtime.h>
#include <cuda_bf16.h>
#include <stdint.h>

#define Tt 8192
#define Dd 1024
#define Ff 4096
#define Oo 1024
#define Ee 4
#define NSs 2
#define N1 24576
#define HN 8192                       // shared H width (2*Ff)
#define MAXT 132                      // max routed M-tiles (16384/128 + 4)
#define RPAD (MAXT * 128)             // padded gathered rows

#define BM 128
#define BN 128
#define BKC 64
#define STAGES 3
#define TILEB (128 * 128)
#define STAGEB (4 * TILEB)
#define SMEM_DYN (STAGES * STAGEB)    // 196608

// ---------------- device scratch (allocation-free) ----------------
__device__ __align__(256) __nv_bfloat16 g_Xh[(size_t)Tt * Dd];
__device__ __align__(256) __nv_bfloat16 g_Xl[(size_t)Tt * Dd];
__device__ __align__(256) __nv_bfloat16 g_W1h[(size_t)N1 * Dd];   // [n][k], slots: sh0,sh1,r0..r3
__device__ __align__(256) __nv_bfloat16 g_W1l[(size_t)N1 * Dd];
__device__ __align__(256) __nv_bfloat16 g_W2h[(size_t)Oo * N1];   // [o][c], c = slot*Ff+f
__device__ __align__(256) __nv_bfloat16 g_W2l[(size_t)Oo * N1];
__device__ __align__(256) __nv_bfloat16 g_Hsh_h[(size_t)Tt * HN]; // shared hidden
__device__ __align__(256) __nv_bfloat16 g_Hsh_l[(size_t)Tt * HN];
__device__ __align__(256) __nv_bfloat16 g_Rh[(size_t)RPAD * Ff];  // routed hidden (gathered)
__device__ __align__(256) __nv_bfloat16 g_Rl[(size_t)RPAD * Ff];
__device__ __align__(256) float g_Rout[(size_t)RPAD * Oo];        // routed expert outputs
__device__ float2 g_tw[Tt];           // top-2 weights
__device__ int2   g_ti[Tt];           // top-2 expert ids
__device__ int2   g_pp[Tt];           // gathered row positions of token's 2 assignments
__device__ int    g_rows[RPAD];       // gathered row -> token id
__device__ int    g_cnt[Ee];
__device__ int    g_fill[Ee];
__device__ int    g_off[Ee];
__device__ int    g_tile_e[MAXT];
__device__ int    g_tile_m0[MAXT];

// ---------------- helpers ----------------
__device__ __forceinline__ uint32_t smem_u32(const void* p) {
    return (uint32_t)__cvta_generic_to_shared(p);
}
__device__ __forceinline__ uint32_t sw128(uint32_t x) { return x ^ ((x >> 3) & 0x70u); }

__device__ __forceinline__ void cp16(uint32_t s, const void* g) {
    asm volatile("cp.async.cg.shared.global [%0], [%1], 16;\n" :: "r"(s), "l"(g));
}
__device__ __forceinline__ void cp_commit() { asm volatile("cp.async.commit_group;\n"); }
template <int N> __device__ __forceinline__ void cp_wait() {
    asm volatile("cp.async.wait_group %0;\n" :: "n"(N));
}
__device__ __forceinline__ void ldsm_x4(uint32_t* r, uint32_t addr) {
    asm volatile("ldmatrix.sync.aligned.m8n8.x4.shared.b16 {%0,%1,%2,%3}, [%4];"
                 : "=r"(r[0]), "=r"(r[1]), "=r"(r[2]), "=r"(r[3]) : "r"(addr));
}
__device__ __forceinline__ void mma16816(float* d, const uint32_t* a, const uint32_t* b) {
    asm volatile(
        "mma.sync.aligned.m16n8k16.row.col.f32.bf16.bf16.f32 "
        "{%0,%1,%2,%3}, {%4,%5,%6,%7}, {%8,%9}, {%0,%1,%2,%3};"
        : "+f"(d[0]), "+f"(d[1]), "+f"(d[2]), "+f"(d[3])
        : "r"(a[0]), "r"(a[1]), "r"(a[2]), "r"(a[3]), "r"(b[0]), "r"(b[1]));
}

// ---------------- routing setup ----------------
__global__ void init_kernel() {
    if (threadIdx.x < Ee) { g_cnt[threadIdx.x] = 0; g_fill[threadIdx.x] = 0; }
}

__global__ void gate_kernel(const float* __restrict__ x,
                            const float* __restrict__ gw,
                            const float* __restrict__ gb) {
    int t = blockIdx.x * (blockDim.x >> 5) + (threadIdx.x >> 5);
    int lane = threadIdx.x & 31;
    if (t >= Tt) return;
    float a0 = 0.f, a1 = 0.f, a2 = 0.f, a3 = 0.f;
    const float* xr = x + (size_t)t * Dd;
    for (int d = lane; d < Dd; d += 32) {
        float xv = xr[d];
        a0 += xv * gw[d * Ee + 0]; a1 += xv * gw[d * Ee + 1];
        a2 += xv * gw[d * Ee + 2]; a3 += xv * gw[d * Ee + 3];
    }
    #pragma unroll
    for (int off = 16; off; off >>= 1) {
        a0 += __shfl_xor_sync(~0u, a0, off); a1 += __shfl_xor_sync(~0u, a1, off);
        a2 += __shfl_xor_sync(~0u, a2, off); a3 += __shfl_xor_sync(~0u, a3, off);
    }
    if (lane == 0) {
        float lg[Ee] = {a0 + gb[0], a1 + gb[1], a2 + gb[2], a3 + gb[3]};
        float mx = fmaxf(fmaxf(lg[0], lg[1]), fmaxf(lg[2], lg[3]));
        float w[Ee]; float s = 0.f;
        #pragma unroll
        for (int e = 0; e < Ee; e++) { w[e] = __expf(lg[e] - mx); s += w[e]; }
        float inv = 1.f / s;
        #pragma unroll
        for (int e = 0; e < Ee; e++) w[e] *= inv;
        int i1 = 0;
        #pragma unroll
        for (int e = 1; e < Ee; e++) if (w[e] > w[i1]) i1 = e;
        int i2 = -1;
        #pragma unroll
        for (int e = 0; e < Ee; e++) {
            if (e == i1) continue;
            if (i2 < 0 || w[e] > w[i2]) i2 = e;
        }
        g_tw[t] = make_float2(w[i1], w[i2]);
        g_ti[t] = make_int2(i1, i2);
        atomicAdd(&g_cnt[i1], 1);
        atomicAdd(&g_cnt[i2], 1);
    }
}

__global__ void setup_kernel() {
    __shared__ int soff[Ee], snt[Ee];
    if (threadIdx.x == 0) {
        int o = 0, tt = 0;
        for (int e = 0; e < Ee; e++) {
            soff[e] = o;
            snt[e] = (g_cnt[e] + 127) >> 7;
            o += snt[e] << 7;
            g_off[e] = soff[e];
        }
        for (int e = 0; e < Ee; e++)
            for (int i = 0; i < snt[e]; i++) {
                g_tile_e[tt] = e;
                g_tile_m0[tt] = soff[e] + (i << 7);
                tt++;
            }
        for (; tt < MAXT; tt++) g_tile_e[tt] = -1;
    }
    __syncthreads();
    for (int e = 0; e < Ee; e++) {
        int base = soff[e], c = g_cnt[e], end = snt[e] << 7;
        for (int i = c + threadIdx.x; i < end; i += blockDim.x) g_rows[base + i] = 0;
    }
}

__global__ void scatter_kernel() {
    int t = blockIdx.x * blockDim.x + threadIdx.x;
    if (t >= Tt) return;
    int2 ii = g_ti[t];
    int p = atomicAdd(&g_fill[ii.x], 1);
    int idx1 = g_off[ii.x] + p;
    g_rows[idx1] = t;
    p = atomicAdd(&g_fill[ii.y], 1);
    int idx2 = g_off[ii.y] + p;
    g_rows[idx2] = t;
    g_pp[t] = make_int2(idx1, idx2);
}

// ---------------- conversions ----------------
__global__ void cvt_x(const float* __restrict__ x) {
    int i = blockIdx.x * blockDim.x + threadIdx.x;
    float v = x[i];
    __nv_bfloat16 h = __float2bfloat16(v);
    g_Xh[i] = h;
    g_Xl[i] = __float2bfloat16(v - __bfloat162float(h));
}

__global__ void cvt_w1(const float* __restrict__ sw1, const float* __restrict__ rw1) {
    __shared__ float t[32][33];
    int nb = blockIdx.x * 32, kb = blockIdx.y * 32;
    int j = nb >> 12, f0 = nb & (Ff - 1);
    const float* W = (j < NSs) ? sw1 + (size_t)j * Dd * Ff : rw1 + (size_t)(j - NSs) * Dd * Ff;
    for (int i = threadIdx.y; i < 32; i += 8)
        t[i][threadIdx.x] = W[(size_t)(kb + i) * Ff + f0 + threadIdx.x];
    __syncthreads();
    for (int i = threadIdx.y; i < 32; i += 8) {
        int n = nb + i, k = kb + threadIdx.x;
        float v = t[threadIdx.x][i];
        __nv_bfloat16 h = __float2bfloat16(v);
        g_W1h[(size_t)n * Dd + k] = h;
        g_W1l[(size_t)n * Dd + k] = __float2bfloat16(v - __bfloat162float(h));
    }
}

__global__ void cvt_w2(const float* __restrict__ sw2, const float* __restrict__ rw2) {
    __shared__ float t[32][33];
    int ob = blockIdx.x * 32, cb = blockIdx.y * 32;
    int j = cb >> 12, f0 = cb & (Ff - 1);
    const float* W = (j < NSs) ? sw2 + (size_t)j * Ff * Oo : rw2 + (size_t)(j - NSs) * Ff * Oo;
    for (int i = threadIdx.y; i < 32; i += 8)
        t[i][threadIdx.x] = W[(size_t)(f0 + i) * Oo + ob + threadIdx.x];
    __syncthreads();
    for (int i = threadIdx.y; i < 32; i += 8) {
        int o = ob + i, c = cb + threadIdx.x;
        float v = t[threadIdx.x][i];
        __nv_bfloat16 h = __float2bfloat16(v);
        g_W2h[(size_t)o * N1 + c] = h;
        g_W2l[(size_t)o * N1 + c] = __float2bfloat16(v - __bfloat162float(h));
    }
}

// ---------------- GEMM machinery ----------------
__device__ __forceinline__ void load_tile256(uint32_t sbase, const __nv_bfloat16* g,
                                             int4 rows, int k0, int pitch, int tid) {
    int c16 = (tid & 7) * 16;
    uint32_t soff = (uint32_t)((tid >> 3) * 128 + c16);
    cp16(sbase + sw128(soff),             (const char*)g + ((size_t)rows.x * pitch + k0) * 2 + c16);
    cp16(sbase + sw128(soff + 32 * 128),  (const char*)g + ((size_t)rows.y * pitch + k0) * 2 + c16);
    cp16(sbase + sw128(soff + 64 * 128),  (const char*)g + ((size_t)rows.z * pitch + k0) * 2 + c16);
    cp16(sbase + sw128(soff + 96 * 128),  (const char*)g + ((size_t)rows.w * pitch + k0) * 2 + c16);
}

__device__ __forceinline__ void load_stage(uint32_t st,
                                           const __nv_bfloat16* Ah, const __nv_bfloat16* Al,
                                           int pitchA, int4 ar,
                                           const __nv_bfloat16* Bh, const __nv_bfloat16* Bl,
                                           int pitchB, int4 br, int k0, int tid) {
    load_tile256(st + 0 * TILEB, Ah, ar, k0, pitchA, tid);
    load_tile256(st + 1 * TILEB, Al, ar, k0, pitchA, tid);
    load_tile256(st + 2 * TILEB, Bh, br, k0, pitchB, tid);
    load_tile256(st + 3 * TILEB, Bl, br, k0, pitchB, tid);
    cp_commit();
}

__device__ __forceinline__ void mainloop(float acc[4][4][4], uint32_t sb,
                                         const __nv_bfloat16* Ah, const __nv_bfloat16* Al,
                                         int pitchA, int4 ar,
                                         const __nv_bfloat16* Bh, const __nv_bfloat16* Bl,
                                         int pitchB, int4 br, int K) {
    const int tid = threadIdx.x;
    const int wid = tid >> 5, lane = tid & 31;
    const int wm = wid >> 2, wn = wid & 3;
    const int NC = K / BKC;

    #pragma unroll
    for (int mi = 0; mi < 4; mi++)
        #pragma unroll
        for (int ni = 0; ni < 4; ni++)
            #pragma unroll
            for (int d = 0; d < 4; d++) acc[mi][ni][d] = 0.f;

    #pragma unroll
    for (int s = 0; s < STAGES; s++)
        load_stage(sb + s * STAGEB, Ah, Al, pitchA, ar, Bh, Bl, pitchB, br, s * BKC, tid);

    const uint32_t aRow = (uint32_t)(wm * 64 + (lane & 15));
    const uint32_t aKb  = (uint32_t)(((lane >> 4) & 1) << 4);
    const uint32_t bRow = (uint32_t)(wn * 32 + (lane & 7) + (((lane >> 4) & 1) << 3));
    const uint32_t bKb  = (uint32_t)(((lane >> 3) & 1) << 4);

    for (int c = 0; c < NC; c++) {
        int b = c - (c / STAGES) * STAGES;
        uint32_t st = sb + b * STAGEB;
        int pend = NC - 1 - c; if (pend > STAGES - 1) pend = STAGES - 1;
        if (pend >= 2) cp_wait<2>(); else if (pend == 1) cp_wait<1>(); else cp_wait<0>();
        __syncthreads();

        #pragma unroll
        for (int ks = 0; ks < 4; ks++) {
            const uint32_t kb = (uint32_t)(ks * 32);
            uint32_t af[2][4][4];
            uint32_t bf[2][4][2];
            #pragma unroll
            for (int mi = 0; mi < 4; mi++) {
                uint32_t off = sw128((aRow + mi * 16) * 128 + kb + aKb);
                ldsm_x4(af[0][mi], st + 0 * TILEB + off);
                ldsm_x4(af[1][mi], st + 1 * TILEB + off);
            }
            #pragma unroll
            for (int n2 = 0; n2 < 2; n2++) {
                uint32_t off = sw128((bRow + n2 * 16) * 128 + kb + bKb);
                uint32_t r[4];
                ldsm_x4(r, st + 2 * TILEB + off);
                bf[0][n2 * 2][0] = r[0]; bf[0][n2 * 2][1] = r[1];
                bf[0][n2 * 2 + 1][0] = r[2]; bf[0][n2 * 2 + 1][1] = r[3];
                ldsm_x4(r, st + 3 * TILEB + off);
                bf[1][n2 * 2][0] = r[0]; bf[1][n2 * 2][1] = r[1];
                bf[1][n2 * 2 + 1][0] = r[2]; bf[1][n2 * 2 + 1][1] = r[3];
            }
            #pragma unroll
            for (int mi = 0; mi < 4; mi++)
                #pragma unroll
                for (int ni = 0; ni < 4; ni++) {
                    mma16816(acc[mi][ni], af[0][mi], bf[0][ni]);
                    mma16816(acc[mi][ni], af[0][mi], bf[1][ni]);
                    mma16816(acc[mi][ni], af[1][mi], bf[0][ni]);
                }
        }
        __syncthreads();
        if (c + STAGES < NC)
            load_stage(st, Ah, Al, pitchA, ar, Bh, Bl, pitchB, br, (c + STAGES) * BKC, tid);
    }
}

__device__ __forceinline__ int4 seq_rows(int base, int tid) {
    int r = base + (tid >> 3);
    return make_int4(r, r + 32, r + 64, r + 96);
}

// ---------------- GEMM1 shared: H_sh = 0.5 * relu(X @ W1_sh + sb1) ----------------
__global__ __launch_bounds__(256, 1)
void gemm1_sh(const float* __restrict__ sb1) {
    extern __shared__ __align__(1024) char smem[];
    uint32_t sb = smem_u32(smem);
    const int m0 = blockIdx.x * BM;
    const int n0 = blockIdx.y * BN;
    const int tid = threadIdx.x;

    float acc[4][4][4];
    mainloop(acc, sb, g_Xh, g_Xl, Dd, seq_rows(m0, tid),
             g_W1h, g_W1l, Dd, seq_rows(n0, tid), Dd);

    const int wid = tid >> 5, lane = tid & 31;
    const int wm = wid >> 2, wn = wid & 3;
    const int j = n0 >> 12, f0 = n0 & (Ff - 1);
    const float* bb = sb1 + j * Ff;

    #pragma unroll
    for (int mi = 0; mi < 4; mi++)
        #pragma unroll
        for (int h = 0; h < 2; h++) {
            const int row = m0 + wm * 64 + mi * 16 + (lane >> 2) + h * 8;
            #pragma unroll
            for (int ni = 0; ni < 4; ni++) {
                const int col = wn * 32 + ni * 8 + (lane & 3) * 2;
                float v0 = fmaxf(acc[mi][ni][h * 2 + 0] + bb[f0 + col], 0.f) * 0.5f;
                float v1 = fmaxf(acc[mi][ni][h * 2 + 1] + bb[f0 + col + 1], 0.f) * 0.5f;
                __nv_bfloat16 h0 = __float2bfloat16(v0);
                __nv_bfloat16 h1 = __float2bfloat16(v1);
                __nv_bfloat162 hv; hv.x = h0; hv.y = h1;
                __nv_bfloat162 lv;
                lv.x = __float2bfloat16(v0 - __bfloat162float(h0));
                lv.y = __float2bfloat16(v1 - __bfloat162float(h1));
                *(__nv_bfloat162*)(g_Hsh_h + (size_t)row * HN + n0 + col) = hv;
                *(__nv_bfloat162*)(g_Hsh_l + (size_t)row * HN + n0 + col) = lv;
            }
        }
}

// ---------------- GEMM1 routed (gathered): R = relu(X[g] @ W1_e + rb1_e) ----------------
__global__ __launch_bounds__(256, 1)
void gemm1_rt(const float* __restrict__ rb1) {
    const int bm = blockIdx.x;
    const int e = g_tile_e[bm];
    if (e < 0) return;
    extern __shared__ __align__(1024) char smem[];
    uint32_t sb = smem_u32(smem);
    const int m0 = g_tile_m0[bm];
    const int n0 = blockIdx.y * BN;
    const int tid = threadIdx.x;

    int rb = m0 + (tid >> 3);
    int4 ar = make_int4(g_rows[rb], g_rows[rb + 32], g_rows[rb + 64], g_rows[rb + 96]);
    const __nv_bfloat16* Wh = g_W1h + (size_t)(NSs + e) * Ff * Dd;
    const __nv_bfloat16* Wl = g_W1l + (size_t)(NSs + e) * Ff * Dd;

    float acc[4][4][4];
    mainloop(acc, sb, g_Xh, g_Xl, Dd, ar, Wh, Wl, Dd, seq_rows(n0, tid), Dd);

    const int wid = tid >> 5, lane = tid & 31;
    const int wm = wid >> 2, wn = wid & 3;
    const float* bb = rb1 + e * Ff + n0;

    #pragma unroll
    for (int mi = 0; mi < 4; mi++)
        #pragma unroll
        for (int h = 0; h < 2; h++) {
            const int row = m0 + wm * 64 + mi * 16 + (lane >> 2) + h * 8;
            #pragma unroll
            for (int ni = 0; ni < 4; ni++) {
                const int col = wn * 32 + ni * 8 + (lane & 3) * 2;
                float v0 = fmaxf(acc[mi][ni][h * 2 + 0] + bb[col], 0.f);
                float v1 = fmaxf(acc[mi][ni][h * 2 + 1] + bb[col + 1], 0.f);
                __nv_bfloat16 h0 = __float2bfloat16(v0);
                __nv_bfloat16 h1 = __float2bfloat16(v1);
                __nv_bfloat162 hv; hv.x = h0; hv.y = h1;
                __nv_bfloat162 lv;
                lv.x = __float2bfloat16(v0 - __bfloat162float(h0));
                lv.y = __float2bfloat16(v1 - __bfloat162float(h1));
                *(__nv_bfloat162*)(g_Rh + (size_t)row * Ff + n0 + col) = hv;
                *(__nv_bfloat162*)(g_Rl + (size_t)row * Ff + n0 + col) = lv;
            }
        }
}

// ---------------- GEMM2 shared: out = H_sh @ W2_sh + 0.5*(sb2_0+sb2_1) ----------------
__global__ __launch_bounds__(256, 1)
void gemm2_sh(const float* __restrict__ sb2, float* __restrict__ out) {
    extern __shared__ __align__(1024) char smem[];
    uint32_t sb = smem_u32(smem);
    const int n0 = blockIdx.x * BN;
    const int m0 = blockIdx.y * BM;
    const int tid = threadIdx.x;

    float acc[4][4][4];
    mainloop(acc, sb, g_Hsh_h, g_Hsh_l, HN, seq_rows(m0, tid),
             g_W2h, g_W2l, N1, seq_rows(n0, tid), HN);

    const int wid = tid >> 5, lane = tid & 31;
    const int wm = wid >> 2, wn = wid & 3;

    #pragma unroll
    for (int mi = 0; mi < 4; mi++)
        #pragma unroll
        for (int h = 0; h < 2; h++) {
            const int row = m0 + wm * 64 + mi * 16 + (lane >> 2) + h * 8;
            #pragma unroll
            for (int ni = 0; ni < 4; ni++) {
                const int col = n0 + wn * 32 + ni * 8 + (lane & 3) * 2;
                float2 v;
                v.x = acc[mi][ni][h * 2 + 0] + 0.5f * (sb2[col] + sb2[Oo + col]);
                v.y = acc[mi][ni][h * 2 + 1] + 0.5f * (sb2[col + 1] + sb2[Oo + col + 1]);
                *(float2*)(out + (size_t)row * Oo + col) = v;
            }
        }
}

// ---------------- GEMM2 routed: Rout = R @ W2_e + rb2_e ----------------
__global__ __launch_bounds__(256, 1)
void gemm2_rt(const float* __restrict__ rb2) {
    const int bm = blockIdx.y;
    const int e = g_tile_e[bm];
    if (e < 0) return;
    extern __shared__ __align__(1024) char smem[];
    uint32_t sb = smem_u32(smem);
    const int m0 = g_tile_m0[bm];
    const int n0 = blockIdx.x * BN;
    const int tid = threadIdx.x;

    const __nv_bfloat16* Wh = g_W2h + (size_t)(NSs + e) * Ff;  // col offset, pitch N1
    const __nv_bfloat16* Wl = g_W2l + (size_t)(NSs + e) * Ff;

    float acc[4][4][4];
    mainloop(acc, sb, g_Rh, g_Rl, Ff, seq_rows(m0, tid), Wh, Wl, N1, seq_rows(n0, tid), Ff);

    const int wid = tid >> 5, lane = tid & 31;
    const int wm = wid >> 2, wn = wid & 3;

    #pragma unroll
    for (int mi = 0; mi < 4; mi++)
        #pragma unroll
        for (int h = 0; h < 2; h++) {
            const int row = m0 + wm * 64 + mi * 16 + (lane >> 2) + h * 8;
            #pragma unroll
            for (int ni = 0; ni < 4; ni++) {
                const int col = n0 + wn * 32 + ni * 8 + (lane & 3) * 2;
                float2 v;
                v.x = acc[mi][ni][h * 2 + 0] + rb2[e * Oo + col];
                v.y = acc[mi][ni][h * 2 + 1] + rb2[e * Oo + col + 1];
                *(float2*)(g_Rout + (size_t)row * Oo + col) = v;
            }
        }
}

// ---------------- combine: out[t] += w1*Rout[p1] + w2*Rout[p2] ----------------
__global__ void combine_kernel(float* __restrict__ out) {
    int t = blockIdx.x;
    int o = threadIdx.x * 4;
    float2 w = g_tw[t];
    int2 p = g_pp[t];
    float4 a  = *(const float4*)(out + (size_t)t * Oo + o);
    float4 r1 = *(const float4*)(g_Rout + (size_t)p.x * Oo + o);
    float4 r2 = *(const float4*)(g_Rout + (size_t)p.y * Oo + o);
    a.x += w.x * r1.x + w.y * r2.x;
    a.y += w.x * r1.y + w.y * r2.y;
    a.z += w.x * r1.z + w.y * r2.z;
    a.w += w.x * r1.w + w.y * r2.w;
    *(float4*)(out + (size_t)t * Oo + o) = a;
}

// ---------------- launch ----------------
extern "C" void kernel_launch(void* const* d_in, const int* in_sizes, int n_in,
                              void* d_out, int out_size) {
    const float* x      = (const float*)d_in[0];
    const float* gate_w = (const float*)d_in[1];
    const float* gate_b = (const float*)d_in[2];
    const float* sw1    = (const float*)d_in[3];
    const float* sb1    = (const float*)d_in[4];
    const float* sw2    = (const float*)d_in[5];
    const float* sb2    = (const float*)d_in[6];
    const float* rw1    = (const float*)d_in[7];
    const float* rb1    = (const float*)d_in[8];
    const float* rw2    = (const float*)d_in[9];
    const float* rb2    = (const float*)d_in[10];
    float* out = (float*)d_out;

    cudaFuncSetAttribute(gemm1_sh, cudaFuncAttributeMaxDynamicSharedMemorySize, SMEM_DYN);
    cudaFuncSetAttribute(gemm1_rt, cudaFuncAttributeMaxDynamicSharedMemorySize, SMEM_DYN);
    cudaFuncSetAttribute(gemm2_sh, cudaFuncAttributeMaxDynamicSharedMemorySize, SMEM_DYN);
    cudaFuncSetAttribute(gemm2_rt, cudaFuncAttributeMaxDynamicSharedMemorySize, SMEM_DYN);

    init_kernel<<<1, 32>>>();
    gate_kernel<<<Tt / 8, 256>>>(x, gate_w, gate_b);
    setup_kernel<<<1, 256>>>();
    scatter_kernel<<<Tt / 256, 256>>>();

    cvt_x<<<(Tt * Dd) / 256, 256>>>(x);
    dim3 bt(32, 8);
    cvt_w1<<<dim3(N1 / 32, Dd / 32), bt>>>(sw1, rw1);
    cvt_w2<<<dim3(Oo / 32, N1 / 32), bt>>>(sw2, rw2);

    gemm1_sh<<<dim3(Tt / BM, HN / BN), 256, SMEM_DYN>>>(sb1);
    gemm1_rt<<<dim3(MAXT, Ff / BN), 256, SMEM_DYN>>>(rb1);
    gemm2_sh<<<dim3(Oo / BN, Tt / BM), 256, SMEM_DYN>>>(sb2, out);
    gemm2_rt<<<dim3(Oo / BN, MAXT), 256, SMEM_DYN>>>(rb2);
    combine_kernel<<<Tt, 256>>>(out);
}

// round 5
// speedup vs baseline: 6.5673x; 1.3005x over previous
#include <cuda_runtime.h>
#include <cuda_bf16.h>
#include <stdint.h>

#define Tt 8192
#define Dd 1024
#define Ff 4096
#define Oo 1024
#define Ee 4
#define NSs 2
#define N1 24576
#define HN 8192
#define MAXT 132
#define RPAD (MAXT * 128)

#define BM 128
#define BN 128
#define BKC 64
#define STAGES 3
#define TILEB (128 * 128)
#define STAGEB (4 * TILEB)
#define SMEM_DYN (STAGES * STAGEB)    // 196608

#define SSCALE 32.0f
#define INV_SSCALE 0.03125f

// ---------------- device scratch (allocation-free) ----------------
__device__ __align__(256) __nv_bfloat16 g_Xh[(size_t)Tt * Dd];
__device__ __align__(256) __nv_bfloat16 g_Xp[(size_t)Tt * Dd];
__device__ __align__(256) __nv_bfloat16 g_W1h[(size_t)N1 * Dd];   // [n][k]
__device__ __align__(256) __nv_bfloat16 g_W1p[(size_t)N1 * Dd];
__device__ __align__(256) __nv_bfloat16 g_W2h[(size_t)Oo * N1];   // [o][c]
__device__ __align__(256) __nv_bfloat16 g_W2p[(size_t)Oo * N1];
__device__ __align__(256) __nv_bfloat16 g_Hsh_h[(size_t)Tt * HN];
__device__ __align__(256) __nv_bfloat16 g_Hsh_p[(size_t)Tt * HN];
__device__ __align__(256) __nv_bfloat16 g_Rh[(size_t)RPAD * Ff];
__device__ __align__(256) __nv_bfloat16 g_Rp[(size_t)RPAD * Ff];
__device__ __align__(256) float g_Rout[(size_t)RPAD * Oo];
__device__ float2 g_tw[Tt];
__device__ int2   g_ti[Tt];
__device__ int2   g_pp[Tt];
__device__ int    g_rows[RPAD];
__device__ int    g_cnt[Ee];
__device__ int    g_fill[Ee];
__device__ int    g_off[Ee];
__device__ int    g_tile_e[MAXT];
__device__ int    g_tile_m0[MAXT];

// ---------------- helpers ----------------
__device__ __forceinline__ uint32_t smem_u32(const void* p) {
    return (uint32_t)__cvta_generic_to_shared(p);
}
__device__ __forceinline__ uint32_t sw128(uint32_t x) { return x ^ ((x >> 3) & 0x70u); }

__device__ __forceinline__ void cp16(uint32_t s, const void* g) {
    asm volatile("cp.async.cg.shared.global [%0], [%1], 16;\n" :: "r"(s), "l"(g));
}
__device__ __forceinline__ void cp_commit() { asm volatile("cp.async.commit_group;\n"); }
template <int N> __device__ __forceinline__ void cp_wait() {
    asm volatile("cp.async.wait_group %0;\n" :: "n"(N));
}
__device__ __forceinline__ void ldsm_x4(uint32_t* r, uint32_t addr) {
    asm volatile("ldmatrix.sync.aligned.m8n8.x4.shared.b16 {%0,%1,%2,%3}, [%4];"
                 : "=r"(r[0]), "=r"(r[1]), "=r"(r[2]), "=r"(r[3]) : "r"(addr));
}
__device__ __forceinline__ void mma16816(float* d, const uint32_t* a, const uint32_t* b) {
    asm volatile(
        "mma.sync.aligned.m16n8k16.row.col.f32.bf16.bf16.f32 "
        "{%0,%1,%2,%3}, {%4,%5,%6,%7}, {%8,%9}, {%0,%1,%2,%3};"
        : "+f"(d[0]), "+f"(d[1]), "+f"(d[2]), "+f"(d[3])
        : "r"(a[0]), "r"(a[1]), "r"(a[2]), "r"(a[3]), "r"(b[0]), "r"(b[1]));
}

__device__ __forceinline__ float comb2(float c1, float c2) {
    return c1 + (c2 - c1) * INV_SSCALE;
}
__device__ __forceinline__ void split_hp(float v, __nv_bfloat16& h, __nv_bfloat16& p) {
    h = __float2bfloat16(v);
    float hf = __bfloat162float(h);
    p = __float2bfloat16(hf + SSCALE * (v - hf));
}

// ---------------- routing setup ----------------
__global__ void init_kernel() {
    if (threadIdx.x < Ee) { g_cnt[threadIdx.x] = 0; g_fill[threadIdx.x] = 0; }
}

__global__ void gate_kernel(const float* __restrict__ x,
                            const float* __restrict__ gw,
                            const float* __restrict__ gb) {
    int t = blockIdx.x * (blockDim.x >> 5) + (threadIdx.x >> 5);
    int lane = threadIdx.x & 31;
    if (t >= Tt) return;
    float a0 = 0.f, a1 = 0.f, a2 = 0.f, a3 = 0.f;
    const float* xr = x + (size_t)t * Dd;
    for (int d = lane; d < Dd; d += 32) {
        float xv = xr[d];
        a0 += xv * gw[d * Ee + 0]; a1 += xv * gw[d * Ee + 1];
        a2 += xv * gw[d * Ee + 2]; a3 += xv * gw[d * Ee + 3];
    }
    #pragma unroll
    for (int off = 16; off; off >>= 1) {
        a0 += __shfl_xor_sync(~0u, a0, off); a1 += __shfl_xor_sync(~0u, a1, off);
        a2 += __shfl_xor_sync(~0u, a2, off); a3 += __shfl_xor_sync(~0u, a3, off);
    }
    if (lane == 0) {
        float lg[Ee] = {a0 + gb[0], a1 + gb[1], a2 + gb[2], a3 + gb[3]};
        float mx = fmaxf(fmaxf(lg[0], lg[1]), fmaxf(lg[2], lg[3]));
        float w[Ee]; float s = 0.f;
        #pragma unroll
        for (int e = 0; e < Ee; e++) { w[e] = __expf(lg[e] - mx); s += w[e]; }
        float inv = 1.f / s;
        #pragma unroll
        for (int e = 0; e < Ee; e++) w[e] *= inv;
        int i1 = 0;
        #pragma unroll
        for (int e = 1; e < Ee; e++) if (w[e] > w[i1]) i1 = e;
        int i2 = -1;
        #pragma unroll
        for (int e = 0; e < Ee; e++) {
            if (e == i1) continue;
            if (i2 < 0 || w[e] > w[i2]) i2 = e;
        }
        g_tw[t] = make_float2(w[i1], w[i2]);
        g_ti[t] = make_int2(i1, i2);
        atomicAdd(&g_cnt[i1], 1);
        atomicAdd(&g_cnt[i2], 1);
    }
}

__global__ void setup_kernel() {
    __shared__ int soff[Ee], snt[Ee];
    if (threadIdx.x == 0) {
        int o = 0, tt = 0;
        for (int e = 0; e < Ee; e++) {
            soff[e] = o;
            snt[e] = (g_cnt[e] + 127) >> 7;
            o += snt[e] << 7;
            g_off[e] = soff[e];
        }
        for (int e = 0; e < Ee; e++)
            for (int i = 0; i < snt[e]; i++) {
                g_tile_e[tt] = e;
                g_tile_m0[tt] = soff[e] + (i << 7);
                tt++;
            }
        for (; tt < MAXT; tt++) g_tile_e[tt] = -1;
    }
    __syncthreads();
    for (int e = 0; e < Ee; e++) {
        int base = soff[e], c = g_cnt[e], end = snt[e] << 7;
        for (int i = c + threadIdx.x; i < end; i += blockDim.x) g_rows[base + i] = 0;
    }
}

__global__ void scatter_kernel() {
    int t = blockIdx.x * blockDim.x + threadIdx.x;
    if (t >= Tt) return;
    int2 ii = g_ti[t];
    int p = atomicAdd(&g_fill[ii.x], 1);
    int idx1 = g_off[ii.x] + p;
    g_rows[idx1] = t;
    p = atomicAdd(&g_fill[ii.y], 1);
    int idx2 = g_off[ii.y] + p;
    g_rows[idx2] = t;
    g_pp[t] = make_int2(idx1, idx2);
}

// ---------------- conversions ----------------
__global__ void cvt_x(const float* __restrict__ x) {
    int i = blockIdx.x * blockDim.x + threadIdx.x;
    float v = x[i];
    __nv_bfloat16 h, p;
    split_hp(v, h, p);
    g_Xh[i] = h;
    g_Xp[i] = p;
}

__global__ void cvt_w1(const float* __restrict__ sw1, const float* __restrict__ rw1) {
    __shared__ float t[32][33];
    int nb = blockIdx.x * 32, kb = blockIdx.y * 32;
    int j = nb >> 12, f0 = nb & (Ff - 1);
    const float* W = (j < NSs) ? sw1 + (size_t)j * Dd * Ff : rw1 + (size_t)(j - NSs) * Dd * Ff;
    for (int i = threadIdx.y; i < 32; i += 8)
        t[i][threadIdx.x] = W[(size_t)(kb + i) * Ff + f0 + threadIdx.x];
    __syncthreads();
    for (int i = threadIdx.y; i < 32; i += 8) {
        int n = nb + i, k = kb + threadIdx.x;
        float v = t[threadIdx.x][i];
        __nv_bfloat16 h, p;
        split_hp(v, h, p);
        g_W1h[(size_t)n * Dd + k] = h;
        g_W1p[(size_t)n * Dd + k] = p;
    }
}

__global__ void cvt_w2(const float* __restrict__ sw2, const float* __restrict__ rw2) {
    __shared__ float t[32][33];
    int ob = blockIdx.x * 32, cb = blockIdx.y * 32;
    int j = cb >> 12, f0 = cb & (Ff - 1);
    const float* W = (j < NSs) ? sw2 + (size_t)j * Ff * Oo : rw2 + (size_t)(j - NSs) * Ff * Oo;
    for (int i = threadIdx.y; i < 32; i += 8)
        t[i][threadIdx.x] = W[(size_t)(f0 + i) * Oo + ob + threadIdx.x];
    __syncthreads();
    for (int i = threadIdx.y; i < 32; i += 8) {
        int o = ob + i, c = cb + threadIdx.x;
        float v = t[threadIdx.x][i];
        __nv_bfloat16 h, p;
        split_hp(v, h, p);
        g_W2h[(size_t)o * N1 + c] = h;
        g_W2p[(size_t)o * N1 + c] = p;
    }
}

// ---------------- GEMM machinery ----------------
__device__ __forceinline__ void load_tile256(uint32_t sbase, const __nv_bfloat16* g,
                                             int4 rows, int k0, int pitch, int tid) {
    int c16 = (tid & 7) * 16;
    uint32_t soff = (uint32_t)((tid >> 3) * 128 + c16);
    cp16(sbase + sw128(soff),             (const char*)g + ((size_t)rows.x * pitch + k0) * 2 + c16);
    cp16(sbase + sw128(soff + 32 * 128),  (const char*)g + ((size_t)rows.y * pitch + k0) * 2 + c16);
    cp16(sbase + sw128(soff + 64 * 128),  (const char*)g + ((size_t)rows.z * pitch + k0) * 2 + c16);
    cp16(sbase + sw128(soff + 96 * 128),  (const char*)g + ((size_t)rows.w * pitch + k0) * 2 + c16);
}

__device__ __forceinline__ void load_stage(uint32_t st,
                                           const __nv_bfloat16* Ah, const __nv_bfloat16* Ap,
                                           int pitchA, int4 ar,
                                           const __nv_bfloat16* Bh, const __nv_bfloat16* Bp,
                                           int pitchB, int4 br, int k0, int tid) {
    load_tile256(st + 0 * TILEB, Ah, ar, k0, pitchA, tid);
    load_tile256(st + 1 * TILEB, Ap, ar, k0, pitchA, tid);
    load_tile256(st + 2 * TILEB, Bh, br, k0, pitchB, tid);
    load_tile256(st + 3 * TILEB, Bp, br, k0, pitchB, tid);
    cp_commit();
}

// Two-accumulator mainloop: acc1 += Ah*Bh, acc2 += Ap*Bp
__device__ __forceinline__ void mainloop(float acc1[4][4][4], float acc2[4][4][4], uint32_t sb,
                                         const __nv_bfloat16* Ah, const __nv_bfloat16* Ap,
                                         int pitchA, int4 ar,
                                         const __nv_bfloat16* Bh, const __nv_bfloat16* Bp,
                                         int pitchB, int4 br, int K) {
    const int tid = threadIdx.x;
    const int wid = tid >> 5, lane = tid & 31;
    const int wm = wid >> 2, wn = wid & 3;
    const int NC = K / BKC;

    #pragma unroll
    for (int mi = 0; mi < 4; mi++)
        #pragma unroll
        for (int ni = 0; ni < 4; ni++)
            #pragma unroll
            for (int d = 0; d < 4; d++) { acc1[mi][ni][d] = 0.f; acc2[mi][ni][d] = 0.f; }

    // prologue: STAGES-1 chunks in flight
    #pragma unroll
    for (int s = 0; s < STAGES - 1; s++)
        load_stage(sb + s * STAGEB, Ah, Ap, pitchA, ar, Bh, Bp, pitchB, br, s * BKC, tid);

    const uint32_t aRow = (uint32_t)(wm * 64 + (lane & 15));
    const uint32_t aKb  = (uint32_t)(((lane >> 4) & 1) << 4);
    const uint32_t bRow = (uint32_t)(wn * 32 + (lane & 7) + (((lane >> 4) & 1) << 3));
    const uint32_t bKb  = (uint32_t)(((lane >> 3) & 1) << 4);

    for (int c = 0; c < NC; c++) {
        uint32_t st = sb + (c - (c / STAGES) * STAGES) * STAGEB;
        cp_wait<STAGES - 2>();
        __syncthreads();
        {   // issue chunk c+STAGES-1 into the buffer freed at iteration c-1
            int cn = c + STAGES - 1;
            if (cn < NC)
                load_stage(sb + (cn - (cn / STAGES) * STAGES) * STAGEB,
                           Ah, Ap, pitchA, ar, Bh, Bp, pitchB, br, cn * BKC, tid);
        }

        #pragma unroll
        for (int ks = 0; ks < 4; ks++) {
            const uint32_t kb = (uint32_t)(ks * 32);
            uint32_t af[4][4];
            uint32_t bf[4][2];
            // phase 1: h * h -> acc1
            #pragma unroll
            for (int mi = 0; mi < 4; mi++)
                ldsm_x4(af[mi], st + 0 * TILEB + sw128((aRow + mi * 16) * 128 + kb + aKb));
            #pragma unroll
            for (int n2 = 0; n2 < 2; n2++) {
                uint32_t r[4];
                ldsm_x4(r, st + 2 * TILEB + sw128((bRow + n2 * 16) * 128 + kb + bKb));
                bf[n2 * 2][0] = r[0]; bf[n2 * 2][1] = r[1];
                bf[n2 * 2 + 1][0] = r[2]; bf[n2 * 2 + 1][1] = r[3];
            }
            #pragma unroll
            for (int mi = 0; mi < 4; mi++)
                #pragma unroll
                for (int ni = 0; ni < 4; ni++)
                    mma16816(acc1[mi][ni], af[mi], bf[ni]);
            // phase 2: p * p -> acc2
            #pragma unroll
            for (int mi = 0; mi < 4; mi++)
                ldsm_x4(af[mi], st + 1 * TILEB + sw128((aRow + mi * 16) * 128 + kb + aKb));
            #pragma unroll
            for (int n2 = 0; n2 < 2; n2++) {
                uint32_t r[4];
                ldsm_x4(r, st + 3 * TILEB + sw128((bRow + n2 * 16) * 128 + kb + bKb));
                bf[n2 * 2][0] = r[0]; bf[n2 * 2][1] = r[1];
                bf[n2 * 2 + 1][0] = r[2]; bf[n2 * 2 + 1][1] = r[3];
            }
            #pragma unroll
            for (int mi = 0; mi < 4; mi++)
                #pragma unroll
                for (int ni = 0; ni < 4; ni++)
                    mma16816(acc2[mi][ni], af[mi], bf[ni]);
        }
    }
}

__device__ __forceinline__ int4 seq_rows(int base, int tid) {
    int r = base + (tid >> 3);
    return make_int4(r, r + 32, r + 64, r + 96);
}

// ---------------- GEMM1 shared: H_sh = 0.5 * relu(X @ W1_sh + sb1) ----------------
__global__ __launch_bounds__(256, 1)
void gemm1_sh(const float* __restrict__ sb1) {
    extern __shared__ __align__(1024) char smem[];
    uint32_t sb = smem_u32(smem);
    const int m0 = blockIdx.x * BM;
    const int n0 = blockIdx.y * BN;
    const int tid = threadIdx.x;

    float acc1[4][4][4], acc2[4][4][4];
    mainloop(acc1, acc2, sb, g_Xh, g_Xp, Dd, seq_rows(m0, tid),
             g_W1h, g_W1p, Dd, seq_rows(n0, tid), Dd);

    const int wid = tid >> 5, lane = tid & 31;
    const int wm = wid >> 2, wn = wid & 3;
    const int j = n0 >> 12, f0 = n0 & (Ff - 1);
    const float* bb = sb1 + j * Ff;

    #pragma unroll
    for (int mi = 0; mi < 4; mi++)
        #pragma unroll
        for (int h = 0; h < 2; h++) {
            const int row = m0 + wm * 64 + mi * 16 + (lane >> 2) + h * 8;
            #pragma unroll
            for (int ni = 0; ni < 4; ni++) {
                const int col = wn * 32 + ni * 8 + (lane & 3) * 2;
                float v0 = comb2(acc1[mi][ni][h * 2 + 0], acc2[mi][ni][h * 2 + 0]);
                float v1 = comb2(acc1[mi][ni][h * 2 + 1], acc2[mi][ni][h * 2 + 1]);
                v0 = fmaxf(v0 + bb[f0 + col], 0.f) * 0.5f;
                v1 = fmaxf(v1 + bb[f0 + col + 1], 0.f) * 0.5f;
                __nv_bfloat162 hv, pv;
                split_hp(v0, hv.x, pv.x);
                split_hp(v1, hv.y, pv.y);
                *(__nv_bfloat162*)(g_Hsh_h + (size_t)row * HN + n0 + col) = hv;
                *(__nv_bfloat162*)(g_Hsh_p + (size_t)row * HN + n0 + col) = pv;
            }
        }
}

// ---------------- GEMM1 routed: R = relu(X[g] @ W1_e + rb1_e) ----------------
__global__ __launch_bounds__(256, 1)
void gemm1_rt(const float* __restrict__ rb1) {
    const int bm = blockIdx.x;
    const int e = g_tile_e[bm];
    if (e < 0) return;
    extern __shared__ __align__(1024) char smem[];
    uint32_t sb = smem_u32(smem);
    const int m0 = g_tile_m0[bm];
    const int n0 = blockIdx.y * BN;
    const int tid = threadIdx.x;

    int rb = m0 + (tid >> 3);
    int4 ar = make_int4(g_rows[rb], g_rows[rb + 32], g_rows[rb + 64], g_rows[rb + 96]);
    const __nv_bfloat16* Wh = g_W1h + (size_t)(NSs + e) * Ff * Dd;
    const __nv_bfloat16* Wp = g_W1p + (size_t)(NSs + e) * Ff * Dd;

    float acc1[4][4][4], acc2[4][4][4];
    mainloop(acc1, acc2, sb, g_Xh, g_Xp, Dd, ar, Wh, Wp, Dd, seq_rows(n0, tid), Dd);

    const int wid = tid >> 5, lane = tid & 31;
    const int wm = wid >> 2, wn = wid & 3;
    const float* bb = rb1 + e * Ff + n0;

    #pragma unroll
    for (int mi = 0; mi < 4; mi++)
        #pragma unroll
        for (int h = 0; h < 2; h++) {
            const int row = m0 + wm * 64 + mi * 16 + (lane >> 2) + h * 8;
            #pragma unroll
            for (int ni = 0; ni < 4; ni++) {
                const int col = wn * 32 + ni * 8 + (lane & 3) * 2;
                float v0 = comb2(acc1[mi][ni][h * 2 + 0], acc2[mi][ni][h * 2 + 0]);
                float v1 = comb2(acc1[mi][ni][h * 2 + 1], acc2[mi][ni][h * 2 + 1]);
                v0 = fmaxf(v0 + bb[col], 0.f);
                v1 = fmaxf(v1 + bb[col + 1], 0.f);
                __nv_bfloat162 hv, pv;
                split_hp(v0, hv.x, pv.x);
                split_hp(v1, hv.y, pv.y);
                *(__nv_bfloat162*)(g_Rh + (size_t)row * Ff + n0 + col) = hv;
                *(__nv_bfloat162*)(g_Rp + (size_t)row * Ff + n0 + col) = pv;
            }
        }
}

// ---------------- GEMM2 shared: out = H_sh @ W2_sh + 0.5*(sb2_0+sb2_1) ----------------
__global__ __launch_bounds__(256, 1)
void gemm2_sh(const float* __restrict__ sb2, float* __restrict__ out) {
    extern __shared__ __align__(1024) char smem[];
    uint32_t sb = smem_u32(smem);
    const int n0 = blockIdx.x * BN;
    const int m0 = blockIdx.y * BM;
    const int tid = threadIdx.x;

    float acc1[4][4][4], acc2[4][4][4];
    mainloop(acc1, acc2, sb, g_Hsh_h, g_Hsh_p, HN, seq_rows(m0, tid),
             g_W2h, g_W2p, N1, seq_rows(n0, tid), HN);

    const int wid = tid >> 5, lane = tid & 31;
    const int wm = wid >> 2, wn = wid & 3;

    #pragma unroll
    for (int mi = 0; mi < 4; mi++)
        #pragma unroll
        for (int h = 0; h < 2; h++) {
            const int row = m0 + wm * 64 + mi * 16 + (lane >> 2) + h * 8;
            #pragma unroll
            for (int ni = 0; ni < 4; ni++) {
                const int col = n0 + wn * 32 + ni * 8 + (lane & 3) * 2;
                float2 v;
                v.x = comb2(acc1[mi][ni][h * 2 + 0], acc2[mi][ni][h * 2 + 0])
                    + 0.5f * (sb2[col] + sb2[Oo + col]);
                v.y = comb2(acc1[mi][ni][h * 2 + 1], acc2[mi][ni][h * 2 + 1])
                    + 0.5f * (sb2[col + 1] + sb2[Oo + col + 1]);
                *(float2*)(out + (size_t)row * Oo + col) = v;
            }
        }
}

// ---------------- GEMM2 routed: Rout = R @ W2_e + rb2_e ----------------
__global__ __launch_bounds__(256, 1)
void gemm2_rt(const float* __restrict__ rb2) {
    const int bm = blockIdx.y;
    const int e = g_tile_e[bm];
    if (e < 0) return;
    extern __shared__ __align__(1024) char smem[];
    uint32_t sb = smem_u32(smem);
    const int m0 = g_tile_m0[bm];
    const int n0 = blockIdx.x * BN;
    const int tid = threadIdx.x;

    const __nv_bfloat16* Wh = g_W2h + (size_t)(NSs + e) * Ff;
    const __nv_bfloat16* Wp = g_W2p + (size_t)(NSs + e) * Ff;

    float acc1[4][4][4], acc2[4][4][4];
    mainloop(acc1, acc2, sb, g_Rh, g_Rp, Ff, seq_rows(m0, tid),
             Wh, Wp, N1, seq_rows(n0, tid), Ff);

    const int wid = tid >> 5, lane = tid & 31;
    const int wm = wid >> 2, wn = wid & 3;

    #pragma unroll
    for (int mi = 0; mi < 4; mi++)
        #pragma unroll
        for (int h = 0; h < 2; h++) {
            const int row = m0 + wm * 64 + mi * 16 + (lane >> 2) + h * 8;
            #pragma unroll
            for (int ni = 0; ni < 4; ni++) {
                const int col = n0 + wn * 32 + ni * 8 + (lane & 3) * 2;
                float2 v;
                v.x = comb2(acc1[mi][ni][h * 2 + 0], acc2[mi][ni][h * 2 + 0]) + rb2[e * Oo + col];
                v.y = comb2(acc1[mi][ni][h * 2 + 1], acc2[mi][ni][h * 2 + 1]) + rb2[e * Oo + col + 1];
                *(float2*)(g_Rout + (size_t)row * Oo + col) = v;
            }
        }
}

// ---------------- combine ----------------
__global__ void combine_kernel(float* __restrict__ out) {
    int t = blockIdx.x;
    int o = threadIdx.x * 4;
    float2 w = g_tw[t];
    int2 p = g_pp[t];
    float4 a  = *(const float4*)(out + (size_t)t * Oo + o);
    float4 r1 = *(const float4*)(g_Rout + (size_t)p.x * Oo + o);
    float4 r2 = *(const float4*)(g_Rout + (size_t)p.y * Oo + o);
    a.x += w.x * r1.x + w.y * r2.x;
    a.y += w.x * r1.y + w.y * r2.y;
    a.z += w.x * r1.z + w.y * r2.z;
    a.w += w.x * r1.w + w.y * r2.w;
    *(float4*)(out + (size_t)t * Oo + o) = a;
}

// ---------------- launch ----------------
extern "C" void kernel_launch(void* const* d_in, const int* in_sizes, int n_in,
                              void* d_out, int out_size) {
    const float* x      = (const float*)d_in[0];
    const float* gate_w = (const float*)d_in[1];
    const float* gate_b = (const float*)d_in[2];
    const float* sw1    = (const float*)d_in[3];
    const float* sb1    = (const float*)d_in[4];
    const float* sw2    = (const float*)d_in[5];
    const float* sb2    = (const float*)d_in[6];
    const float* rw1    = (const float*)d_in[7];
    const float* rb1    = (const float*)d_in[8];
    const float* rw2    = (const float*)d_in[9];
    const float* rb2    = (const float*)d_in[10];
    float* out = (float*)d_out;

    cudaFuncSetAttribute(gemm1_sh, cudaFuncAttributeMaxDynamicSharedMemorySize, SMEM_DYN);
    cudaFuncSetAttribute(gemm1_rt, cudaFuncAttributeMaxDynamicSharedMemorySize, SMEM_DYN);
    cudaFuncSetAttribute(gemm2_sh, cudaFuncAttributeMaxDynamicSharedMemorySize, SMEM_DYN);
    cudaFuncSetAttribute(gemm2_rt, cudaFuncAttributeMaxDynamicSharedMemorySize, SMEM_DYN);

    init_kernel<<<1, 32>>>();
    gate_kernel<<<Tt / 8, 256>>>(x, gate_w, gate_b);
    setup_kernel<<<1, 256>>>();
    scatter_kernel<<<Tt / 256, 256>>>();

    cvt_x<<<(Tt * Dd) / 256, 256>>>(x);
    dim3 bt(32, 8);
    cvt_w1<<<dim3(N1 / 32, Dd / 32), bt>>>(sw1, rw1);
    cvt_w2<<<dim3(Oo / 32, N1 / 32), bt>>>(sw2, rw2);

    gemm1_sh<<<dim3(Tt / BM, HN / BN), 256, SMEM_DYN>>>(sb1);
    gemm1_rt<<<dim3(MAXT, Ff / BN), 256, SMEM_DYN>>>(rb1);
    gemm2_sh<<<dim3(Oo / BN, Tt / BM), 256, SMEM_DYN>>>(sb2, out);
    gemm2_rt<<<dim3(Oo / BN, MAXT), 256, SMEM_DYN>>>(rb2);
    combine_kernel<<<Tt, 256>>>(out);
}

// round 6
// speedup vs baseline: 8.4564x; 1.2876x over previous
#include <cuda_runtime.h>
#include <cuda_fp16.h>
#include <stdint.h>

#define Tt 8192
#define Dd 1024
#define Ff 4096
#define Oo 1024
#define Ee 4
#define NSs 2
#define N1 24576
#define HN 8192
#define MAXT 132
#define RPAD (MAXT * 128)

#define BM 128
#define BN 128
#define BKC 64
#define TILEB (128 * 128)

// GEMM1 (split operands): 4 tiles/stage, 3 stages
#define STG2 3
#define STAGEB2 (4 * TILEB)
#define SMEM_G1 (STG2 * STAGEB2)      // 196608
// GEMM2 (single operands): 2 tiles/stage, 5 stages
#define STG1 5
#define STAGEB1 (2 * TILEB)
#define SMEM_G2 (STG1 * STAGEB1)      // 163840

#define SSCALE 64.0f
#define INV_SSCALE 0.015625f

// ---------------- device scratch (allocation-free) ----------------
__device__ __align__(256) __half g_Xh[(size_t)Tt * Dd];
__device__ __align__(256) __half g_Xp[(size_t)Tt * Dd];
__device__ __align__(256) __half g_W1h[(size_t)N1 * Dd];   // [n][k]
__device__ __align__(256) __half g_W1p[(size_t)N1 * Dd];
__device__ __align__(256) __half g_W2[(size_t)Oo * N1];    // [o][c], single fp16
__device__ __align__(256) __half g_Hsh[(size_t)Tt * HN];   // shared hidden, single fp16
__device__ __align__(256) __half g_R[(size_t)RPAD * Ff];   // routed hidden, single fp16
__device__ __align__(256) float g_Rout[(size_t)RPAD * Oo];
__device__ float2 g_tw[Tt];
__device__ int2   g_ti[Tt];
__device__ int2   g_pp[Tt];
__device__ int    g_rows[RPAD];
__device__ int    g_cnt[Ee];
__device__ int    g_fill[Ee];
__device__ int    g_off[Ee];
__device__ int    g_tile_e[MAXT];
__device__ int    g_tile_m0[MAXT];

// ---------------- helpers ----------------
__device__ __forceinline__ uint32_t smem_u32(const void* p) {
    return (uint32_t)__cvta_generic_to_shared(p);
}
__device__ __forceinline__ uint32_t sw128(uint32_t x) { return x ^ ((x >> 3) & 0x70u); }

__device__ __forceinline__ void cp16(uint32_t s, const void* g) {
    asm volatile("cp.async.cg.shared.global [%0], [%1], 16;\n" :: "r"(s), "l"(g));
}
__device__ __forceinline__ void cp_commit() { asm volatile("cp.async.commit_group;\n"); }
template <int N> __device__ __forceinline__ void cp_wait() {
    asm volatile("cp.async.wait_group %0;\n" :: "n"(N));
}
__device__ __forceinline__ void ldsm_x4(uint32_t* r, uint32_t addr) {
    asm volatile("ldmatrix.sync.aligned.m8n8.x4.shared.b16 {%0,%1,%2,%3}, [%4];"
                 : "=r"(r[0]), "=r"(r[1]), "=r"(r[2]), "=r"(r[3]) : "r"(addr));
}
__device__ __forceinline__ void mma16816(float* d, const uint32_t* a, const uint32_t* b) {
    asm volatile(
        "mma.sync.aligned.m16n8k16.row.col.f32.f16.f16.f32 "
        "{%0,%1,%2,%3}, {%4,%5,%6,%7}, {%8,%9}, {%0,%1,%2,%3};"
        : "+f"(d[0]), "+f"(d[1]), "+f"(d[2]), "+f"(d[3])
        : "r"(a[0]), "r"(a[1]), "r"(a[2]), "r"(a[3]), "r"(b[0]), "r"(b[1]));
}

__device__ __forceinline__ float comb2(float c1, float c2) {
    return c1 + (c2 - c1) * INV_SSCALE;
}
__device__ __forceinline__ void split_hp(float v, __half& h, __half& p) {
    h = __float2half_rn(v);
    float hf = __half2float(h);
    p = __float2half_rn(hf + SSCALE * (v - hf));
}

// ---------------- routing setup ----------------
__global__ void init_kernel() {
    if (threadIdx.x < Ee) { g_cnt[threadIdx.x] = 0; g_fill[threadIdx.x] = 0; }
}

__global__ void gate_kernel(const float* __restrict__ x,
                            const float* __restrict__ gw,
                            const float* __restrict__ gb) {
    int t = blockIdx.x * (blockDim.x >> 5) + (threadIdx.x >> 5);
    int lane = threadIdx.x & 31;
    if (t >= Tt) return;
    float a0 = 0.f, a1 = 0.f, a2 = 0.f, a3 = 0.f;
    const float* xr = x + (size_t)t * Dd;
    for (int d = lane; d < Dd; d += 32) {
        float xv = xr[d];
        a0 += xv * gw[d * Ee + 0]; a1 += xv * gw[d * Ee + 1];
        a2 += xv * gw[d * Ee + 2]; a3 += xv * gw[d * Ee + 3];
    }
    #pragma unroll
    for (int off = 16; off; off >>= 1) {
        a0 += __shfl_xor_sync(~0u, a0, off); a1 += __shfl_xor_sync(~0u, a1, off);
        a2 += __shfl_xor_sync(~0u, a2, off); a3 += __shfl_xor_sync(~0u, a3, off);
    }
    if (lane == 0) {
        float lg[Ee] = {a0 + gb[0], a1 + gb[1], a2 + gb[2], a3 + gb[3]};
        float mx = fmaxf(fmaxf(lg[0], lg[1]), fmaxf(lg[2], lg[3]));
        float w[Ee]; float s = 0.f;
        #pragma unroll
        for (int e = 0; e < Ee; e++) { w[e] = __expf(lg[e] - mx); s += w[e]; }
        float inv = 1.f / s;
        #pragma unroll
        for (int e = 0; e < Ee; e++) w[e] *= inv;
        int i1 = 0;
        #pragma unroll
        for (int e = 1; e < Ee; e++) if (w[e] > w[i1]) i1 = e;
        int i2 = -1;
        #pragma unroll
        for (int e = 0; e < Ee; e++) {
            if (e == i1) continue;
            if (i2 < 0 || w[e] > w[i2]) i2 = e;
        }
        g_tw[t] = make_float2(w[i1], w[i2]);
        g_ti[t] = make_int2(i1, i2);
        atomicAdd(&g_cnt[i1], 1);
        atomicAdd(&g_cnt[i2], 1);
    }
}

__global__ void setup_kernel() {
    __shared__ int soff[Ee], snt[Ee];
    if (threadIdx.x == 0) {
        int o = 0, tt = 0;
        for (int e = 0; e < Ee; e++) {
            soff[e] = o;
            snt[e] = (g_cnt[e] + 127) >> 7;
            o += snt[e] << 7;
            g_off[e] = soff[e];
        }
        for (int e = 0; e < Ee; e++)
            for (int i = 0; i < snt[e]; i++) {
                g_tile_e[tt] = e;
                g_tile_m0[tt] = soff[e] + (i << 7);
                tt++;
            }
        for (; tt < MAXT; tt++) g_tile_e[tt] = -1;
    }
    __syncthreads();
    for (int e = 0; e < Ee; e++) {
        int base = soff[e], c = g_cnt[e], end = snt[e] << 7;
        for (int i = c + threadIdx.x; i < end; i += blockDim.x) g_rows[base + i] = 0;
    }
}

__global__ void scatter_kernel() {
    int t = blockIdx.x * blockDim.x + threadIdx.x;
    if (t >= Tt) return;
    int2 ii = g_ti[t];
    int p = atomicAdd(&g_fill[ii.x], 1);
    int idx1 = g_off[ii.x] + p;
    g_rows[idx1] = t;
    p = atomicAdd(&g_fill[ii.y], 1);
    int idx2 = g_off[ii.y] + p;
    g_rows[idx2] = t;
    g_pp[t] = make_int2(idx1, idx2);
}

// ---------------- conversions ----------------
__global__ void cvt_x(const float* __restrict__ x) {
    int i = blockIdx.x * blockDim.x + threadIdx.x;
    float v = x[i];
    __half h, p;
    split_hp(v, h, p);
    g_Xh[i] = h;
    g_Xp[i] = p;
}

__global__ void cvt_w1(const float* __restrict__ sw1, const float* __restrict__ rw1) {
    __shared__ float t[32][33];
    int nb = blockIdx.x * 32, kb = blockIdx.y * 32;
    int j = nb >> 12, f0 = nb & (Ff - 1);
    const float* W = (j < NSs) ? sw1 + (size_t)j * Dd * Ff : rw1 + (size_t)(j - NSs) * Dd * Ff;
    for (int i = threadIdx.y; i < 32; i += 8)
        t[i][threadIdx.x] = W[(size_t)(kb + i) * Ff + f0 + threadIdx.x];
    __syncthreads();
    for (int i = threadIdx.y; i < 32; i += 8) {
        int n = nb + i, k = kb + threadIdx.x;
        float v = t[threadIdx.x][i];
        __half h, p;
        split_hp(v, h, p);
        g_W1h[(size_t)n * Dd + k] = h;
        g_W1p[(size_t)n * Dd + k] = p;
    }
}

__global__ void cvt_w2(const float* __restrict__ sw2, const float* __restrict__ rw2) {
    __shared__ float t[32][33];
    int ob = blockIdx.x * 32, cb = blockIdx.y * 32;
    int j = cb >> 12, f0 = cb & (Ff - 1);
    const float* W = (j < NSs) ? sw2 + (size_t)j * Ff * Oo : rw2 + (size_t)(j - NSs) * Ff * Oo;
    for (int i = threadIdx.y; i < 32; i += 8)
        t[i][threadIdx.x] = W[(size_t)(f0 + i) * Oo + ob + threadIdx.x];
    __syncthreads();
    for (int i = threadIdx.y; i < 32; i += 8) {
        int o = ob + i, c = cb + threadIdx.x;
        g_W2[(size_t)o * N1 + c] = __float2half_rn(t[threadIdx.x][i]);
    }
}

// ---------------- GEMM machinery ----------------
__device__ __forceinline__ void load_tile256(uint32_t sbase, const __half* g,
                                             int4 rows, int k0, int pitch, int tid) {
    int c16 = (tid & 7) * 16;
    uint32_t soff = (uint32_t)((tid >> 3) * 128 + c16);
    cp16(sbase + sw128(soff),             (const char*)g + ((size_t)rows.x * pitch + k0) * 2 + c16);
    cp16(sbase + sw128(soff + 32 * 128),  (const char*)g + ((size_t)rows.y * pitch + k0) * 2 + c16);
    cp16(sbase + sw128(soff + 64 * 128),  (const char*)g + ((size_t)rows.z * pitch + k0) * 2 + c16);
    cp16(sbase + sw128(soff + 96 * 128),  (const char*)g + ((size_t)rows.w * pitch + k0) * 2 + c16);
}

// ---- split (GEMM1) path: 4 tiles/stage, two accumulators ----
__device__ __forceinline__ void load_stage2(uint32_t st,
                                            const __half* Ah, const __half* Ap,
                                            int pitchA, int4 ar,
                                            const __half* Bh, const __half* Bp,
                                            int pitchB, int4 br, int k0, int tid) {
    load_tile256(st + 0 * TILEB, Ah, ar, k0, pitchA, tid);
    load_tile256(st + 1 * TILEB, Ap, ar, k0, pitchA, tid);
    load_tile256(st + 2 * TILEB, Bh, br, k0, pitchB, tid);
    load_tile256(st + 3 * TILEB, Bp, br, k0, pitchB, tid);
    cp_commit();
}

__device__ __forceinline__ void mainloop2(float acc1[4][4][4], float acc2[4][4][4], uint32_t sb,
                                          const __half* Ah, const __half* Ap,
                                          int pitchA, int4 ar,
                                          const __half* Bh, const __half* Bp,
                                          int pitchB, int4 br, int K) {
    const int tid = threadIdx.x;
    const int wid = tid >> 5, lane = tid & 31;
    const int wm = wid >> 2, wn = wid & 3;
    const int NC = K / BKC;

    #pragma unroll
    for (int mi = 0; mi < 4; mi++)
        #pragma unroll
        for (int ni = 0; ni < 4; ni++)
            #pragma unroll
            for (int d = 0; d < 4; d++) { acc1[mi][ni][d] = 0.f; acc2[mi][ni][d] = 0.f; }

    #pragma unroll
    for (int s = 0; s < STG2 - 1; s++)
        load_stage2(sb + s * STAGEB2, Ah, Ap, pitchA, ar, Bh, Bp, pitchB, br, s * BKC, tid);

    const uint32_t aRow = (uint32_t)(wm * 64 + (lane & 15));
    const uint32_t aKb  = (uint32_t)(((lane >> 4) & 1) << 4);
    const uint32_t bRow = (uint32_t)(wn * 32 + (lane & 7) + (((lane >> 4) & 1) << 3));
    const uint32_t bKb  = (uint32_t)(((lane >> 3) & 1) << 4);

    for (int c = 0; c < NC; c++) {
        uint32_t st = sb + (c - (c / STG2) * STG2) * STAGEB2;
        cp_wait<STG2 - 2>();
        __syncthreads();
        {
            int cn = c + STG2 - 1;
            if (cn < NC)
                load_stage2(sb + (cn - (cn / STG2) * STG2) * STAGEB2,
                            Ah, Ap, pitchA, ar, Bh, Bp, pitchB, br, cn * BKC, tid);
        }

        #pragma unroll
        for (int ks = 0; ks < 4; ks++) {
            const uint32_t kb = (uint32_t)(ks * 32);
            uint32_t af[4][4];
            uint32_t bf[4][2];
            #pragma unroll
            for (int mi = 0; mi < 4; mi++)
                ldsm_x4(af[mi], st + 0 * TILEB + sw128((aRow + mi * 16) * 128 + kb + aKb));
            #pragma unroll
            for (int n2 = 0; n2 < 2; n2++) {
                uint32_t r[4];
                ldsm_x4(r, st + 2 * TILEB + sw128((bRow + n2 * 16) * 128 + kb + bKb));
                bf[n2 * 2][0] = r[0]; bf[n2 * 2][1] = r[1];
                bf[n2 * 2 + 1][0] = r[2]; bf[n2 * 2 + 1][1] = r[3];
            }
            #pragma unroll
            for (int mi = 0; mi < 4; mi++)
                #pragma unroll
                for (int ni = 0; ni < 4; ni++)
                    mma16816(acc1[mi][ni], af[mi], bf[ni]);
            #pragma unroll
            for (int mi = 0; mi < 4; mi++)
                ldsm_x4(af[mi], st + 1 * TILEB + sw128((aRow + mi * 16) * 128 + kb + aKb));
            #pragma unroll
            for (int n2 = 0; n2 < 2; n2++) {
                uint32_t r[4];
                ldsm_x4(r, st + 3 * TILEB + sw128((bRow + n2 * 16) * 128 + kb + bKb));
                bf[n2 * 2][0] = r[0]; bf[n2 * 2][1] = r[1];
                bf[n2 * 2 + 1][0] = r[2]; bf[n2 * 2 + 1][1] = r[3];
            }
            #pragma unroll
            for (int mi = 0; mi < 4; mi++)
                #pragma unroll
                for (int ni = 0; ni < 4; ni++)
                    mma16816(acc2[mi][ni], af[mi], bf[ni]);
        }
    }
}

// ---- single (GEMM2) path: 2 tiles/stage, one accumulator ----
__device__ __forceinline__ void load_stage1(uint32_t st,
                                            const __half* A, int pitchA, int4 ar,
                                            const __half* B, int pitchB, int4 br,
                                            int k0, int tid) {
    load_tile256(st + 0 * TILEB, A, ar, k0, pitchA, tid);
    load_tile256(st + 1 * TILEB, B, br, k0, pitchB, tid);
    cp_commit();
}

__device__ __forceinline__ void mainloop1(float acc[4][4][4], uint32_t sb,
                                          const __half* A, int pitchA, int4 ar,
                                          const __half* B, int pitchB, int4 br, int K) {
    const int tid = threadIdx.x;
    const int wid = tid >> 5, lane = tid & 31;
    const int wm = wid >> 2, wn = wid & 3;
    const int NC = K / BKC;

    #pragma unroll
    for (int mi = 0; mi < 4; mi++)
        #pragma unroll
        for (int ni = 0; ni < 4; ni++)
            #pragma unroll
            for (int d = 0; d < 4; d++) acc[mi][ni][d] = 0.f;

    #pragma unroll
    for (int s = 0; s < STG1 - 1; s++)
        load_stage1(sb + s * STAGEB1, A, pitchA, ar, B, pitchB, br, s * BKC, tid);

    const uint32_t aRow = (uint32_t)(wm * 64 + (lane & 15));
    const uint32_t aKb  = (uint32_t)(((lane >> 4) & 1) << 4);
    const uint32_t bRow = (uint32_t)(wn * 32 + (lane & 7) + (((lane >> 4) & 1) << 3));
    const uint32_t bKb  = (uint32_t)(((lane >> 3) & 1) << 4);

    for (int c = 0; c < NC; c++) {
        uint32_t st = sb + (c - (c / STG1) * STG1) * STAGEB1;
        cp_wait<STG1 - 2>();
        __syncthreads();
        {
            int cn = c + STG1 - 1;
            if (cn < NC)
                load_stage1(sb + (cn - (cn / STG1) * STG1) * STAGEB1,
                            A, pitchA, ar, B, pitchB, br, cn * BKC, tid);
        }

        #pragma unroll
        for (int ks = 0; ks < 4; ks++) {
            const uint32_t kb = (uint32_t)(ks * 32);
            uint32_t af[4][4];
            uint32_t bf[4][2];
            #pragma unroll
            for (int mi = 0; mi < 4; mi++)
                ldsm_x4(af[mi], st + 0 * TILEB + sw128((aRow + mi * 16) * 128 + kb + aKb));
            #pragma unroll
            for (int n2 = 0; n2 < 2; n2++) {
                uint32_t r[4];
                ldsm_x4(r, st + 1 * TILEB + sw128((bRow + n2 * 16) * 128 + kb + bKb));
                bf[n2 * 2][0] = r[0]; bf[n2 * 2][1] = r[1];
                bf[n2 * 2 + 1][0] = r[2]; bf[n2 * 2 + 1][1] = r[3];
            }
            #pragma unroll
            for (int mi = 0; mi < 4; mi++)
                #pragma unroll
                for (int ni = 0; ni < 4; ni++)
                    mma16816(acc[mi][ni], af[mi], bf[ni]);
        }
    }
}

__device__ __forceinline__ int4 seq_rows(int base, int tid) {
    int r = base + (tid >> 3);
    return make_int4(r, r + 32, r + 64, r + 96);
}

// ---------------- GEMM1 shared: H_sh = 0.5 * relu(X @ W1_sh + sb1) ----------------
__global__ __launch_bounds__(256, 1)
void gemm1_sh(const float* __restrict__ sb1) {
    extern __shared__ __align__(1024) char smem[];
    uint32_t sb = smem_u32(smem);
    const int m0 = blockIdx.x * BM;
    const int n0 = blockIdx.y * BN;
    const int tid = threadIdx.x;

    float acc1[4][4][4], acc2[4][4][4];
    mainloop2(acc1, acc2, sb, g_Xh, g_Xp, Dd, seq_rows(m0, tid),
              g_W1h, g_W1p, Dd, seq_rows(n0, tid), Dd);

    const int wid = tid >> 5, lane = tid & 31;
    const int wm = wid >> 2, wn = wid & 3;
    const int j = n0 >> 12, f0 = n0 & (Ff - 1);
    const float* bb = sb1 + j * Ff;

    #pragma unroll
    for (int mi = 0; mi < 4; mi++)
        #pragma unroll
        for (int h = 0; h < 2; h++) {
            const int row = m0 + wm * 64 + mi * 16 + (lane >> 2) + h * 8;
            #pragma unroll
            for (int ni = 0; ni < 4; ni++) {
                const int col = wn * 32 + ni * 8 + (lane & 3) * 2;
                float v0 = comb2(acc1[mi][ni][h * 2 + 0], acc2[mi][ni][h * 2 + 0]);
                float v1 = comb2(acc1[mi][ni][h * 2 + 1], acc2[mi][ni][h * 2 + 1]);
                v0 = fmaxf(v0 + bb[f0 + col], 0.f) * 0.5f;
                v1 = fmaxf(v1 + bb[f0 + col + 1], 0.f) * 0.5f;
                __half2 hv;
                hv.x = __float2half_rn(v0);
                hv.y = __float2half_rn(v1);
                *(__half2*)(g_Hsh + (size_t)row * HN + n0 + col) = hv;
            }
        }
}

// ---------------- GEMM1 routed: R = relu(X[g] @ W1_e + rb1_e) ----------------
__global__ __launch_bounds__(256, 1)
void gemm1_rt(const float* __restrict__ rb1) {
    const int bm = blockIdx.x;
    const int e = g_tile_e[bm];
    if (e < 0) return;
    extern __shared__ __align__(1024) char smem[];
    uint32_t sb = smem_u32(smem);
    const int m0 = g_tile_m0[bm];
    const int n0 = blockIdx.y * BN;
    const int tid = threadIdx.x;

    int rb = m0 + (tid >> 3);
    int4 ar = make_int4(g_rows[rb], g_rows[rb + 32], g_rows[rb + 64], g_rows[rb + 96]);
    const __half* Wh = g_W1h + (size_t)(NSs + e) * Ff * Dd;
    const __half* Wp = g_W1p + (size_t)(NSs + e) * Ff * Dd;

    float acc1[4][4][4], acc2[4][4][4];
    mainloop2(acc1, acc2, sb, g_Xh, g_Xp, Dd, ar, Wh, Wp, Dd, seq_rows(n0, tid), Dd);

    const int wid = tid >> 5, lane = tid & 31;
    const int wm = wid >> 2, wn = wid & 3;
    const float* bb = rb1 + e * Ff + n0;

    #pragma unroll
    for (int mi = 0; mi < 4; mi++)
        #pragma unroll
        for (int h = 0; h < 2; h++) {
            const int row = m0 + wm * 64 + mi * 16 + (lane >> 2) + h * 8;
            #pragma unroll
            for (int ni = 0; ni < 4; ni++) {
                const int col = wn * 32 + ni * 8 + (lane & 3) * 2;
                float v0 = comb2(acc1[mi][ni][h * 2 + 0], acc2[mi][ni][h * 2 + 0]);
                float v1 = comb2(acc1[mi][ni][h * 2 + 1], acc2[mi][ni][h * 2 + 1]);
                v0 = fmaxf(v0 + bb[col], 0.f);
                v1 = fmaxf(v1 + bb[col + 1], 0.f);
                __half2 hv;
                hv.x = __float2half_rn(v0);
                hv.y = __float2half_rn(v1);
                *(__half2*)(g_R + (size_t)row * Ff + n0 + col) = hv;
            }
        }
}

// ---------------- GEMM2 shared: out = H_sh @ W2_sh + 0.5*(sb2_0+sb2_1) ----------------
__global__ __launch_bounds__(256, 1)
void gemm2_sh(const float* __restrict__ sb2, float* __restrict__ out) {
    extern __shared__ __align__(1024) char smem[];
    uint32_t sb = smem_u32(smem);
    const int n0 = blockIdx.x * BN;
    const int m0 = blockIdx.y * BM;
    const int tid = threadIdx.x;

    float acc[4][4][4];
    mainloop1(acc, sb, g_Hsh, HN, seq_rows(m0, tid),
              g_W2, N1, seq_rows(n0, tid), HN);

    const int wid = tid >> 5, lane = tid & 31;
    const int wm = wid >> 2, wn = wid & 3;

    #pragma unroll
    for (int mi = 0; mi < 4; mi++)
        #pragma unroll
        for (int h = 0; h < 2; h++) {
            const int row = m0 + wm * 64 + mi * 16 + (lane >> 2) + h * 8;
            #pragma unroll
            for (int ni = 0; ni < 4; ni++) {
                const int col = n0 + wn * 32 + ni * 8 + (lane & 3) * 2;
                float2 v;
                v.x = acc[mi][ni][h * 2 + 0] + 0.5f * (sb2[col] + sb2[Oo + col]);
                v.y = acc[mi][ni][h * 2 + 1] + 0.5f * (sb2[col + 1] + sb2[Oo + col + 1]);
                *(float2*)(out + (size_t)row * Oo + col) = v;
            }
        }
}

// ---------------- GEMM2 routed: Rout = R @ W2_e + rb2_e ----------------
__global__ __launch_bounds__(256, 1)
void gemm2_rt(const float* __restrict__ rb2) {
    const int bm = blockIdx.y;
    const int e = g_tile_e[bm];
    if (e < 0) return;
    extern __shared__ __align__(1024) char smem[];
    uint32_t sb = smem_u32(smem);
    const int m0 = g_tile_m0[bm];
    const int n0 = blockIdx.x * BN;
    const int tid = threadIdx.x;

    const __half* W = g_W2 + (size_t)(NSs + e) * Ff;

    float acc[4][4][4];
    mainloop1(acc, sb, g_R, Ff, seq_rows(m0, tid), W, N1, seq_rows(n0, tid), Ff);

    const int wid = tid >> 5, lane = tid & 31;
    const int wm = wid >> 2, wn = wid & 3;

    #pragma unroll
    for (int mi = 0; mi < 4; mi++)
        #pragma unroll
        for (int h = 0; h < 2; h++) {
            const int row = m0 + wm * 64 + mi * 16 + (lane >> 2) + h * 8;
            #pragma unroll
            for (int ni = 0; ni < 4; ni++) {
                const int col = n0 + wn * 32 + ni * 8 + (lane & 3) * 2;
                float2 v;
                v.x = acc[mi][ni][h * 2 + 0] + rb2[e * Oo + col];
                v.y = acc[mi][ni][h * 2 + 1] + rb2[e * Oo + col + 1];
                *(float2*)(g_Rout + (size_t)row * Oo + col) = v;
            }
        }
}

// ---------------- combine ----------------
__global__ void combine_kernel(float* __restrict__ out) {
    int t = blockIdx.x;
    int o = threadIdx.x * 4;
    float2 w = g_tw[t];
    int2 p = g_pp[t];
    float4 a  = *(const float4*)(out + (size_t)t * Oo + o);
    float4 r1 = *(const float4*)(g_Rout + (size_t)p.x * Oo + o);
    float4 r2 = *(const float4*)(g_Rout + (size_t)p.y * Oo + o);
    a.x += w.x * r1.x + w.y * r2.x;
    a.y += w.x * r1.y + w.y * r2.y;
    a.z += w.x * r1.z + w.y * r2.z;
    a.w += w.x * r1.w + w.y * r2.w;
    *(float4*)(out + (size_t)t * Oo + o) = a;
}

// ---------------- launch ----------------
extern "C" void kernel_launch(void* const* d_in, const int* in_sizes, int n_in,
                              void* d_out, int out_size) {
    const float* x      = (const float*)d_in[0];
    const float* gate_w = (const float*)d_in[1];
    const float* gate_b = (const float*)d_in[2];
    const float* sw1    = (const float*)d_in[3];
    const float* sb1    = (const float*)d_in[4];
    const float* sw2    = (const float*)d_in[5];
    const float* sb2    = (const float*)d_in[6];
    const float* rw1    = (const float*)d_in[7];
    const float* rb1    = (const float*)d_in[8];
    const float* rw2    = (const float*)d_in[9];
    const float* rb2    = (const float*)d_in[10];
    float* out = (float*)d_out;

    cudaFuncSetAttribute(gemm1_sh, cudaFuncAttributeMaxDynamicSharedMemorySize, SMEM_G1);
    cudaFuncSetAttribute(gemm1_rt, cudaFuncAttributeMaxDynamicSharedMemorySize, SMEM_G1);
    cudaFuncSetAttribute(gemm2_sh, cudaFuncAttributeMaxDynamicSharedMemorySize, SMEM_G2);
    cudaFuncSetAttribute(gemm2_rt, cudaFuncAttributeMaxDynamicSharedMemorySize, SMEM_G2);

    init_kernel<<<1, 32>>>();
    gate_kernel<<<Tt / 8, 256>>>(x, gate_w, gate_b);
    setup_kernel<<<1, 256>>>();
    scatter_kernel<<<Tt / 256, 256>>>();

    cvt_x<<<(Tt * Dd) / 256, 256>>>(x);
    dim3 bt(32, 8);
    cvt_w1<<<dim3(N1 / 32, Dd / 32), bt>>>(sw1, rw1);
    cvt_w2<<<dim3(Oo / 32, N1 / 32), bt>>>(sw2, rw2);

    gemm1_sh<<<dim3(Tt / BM, HN / BN), 256, SMEM_G1>>>(sb1);
    gemm1_rt<<<dim3(MAXT, Ff / BN), 256, SMEM_G1>>>(rb1);
    gemm2_sh<<<dim3(Oo / BN, Tt / BM), 256, SMEM_G2>>>(sb2, out);
    gemm2_rt<<<dim3(Oo / BN, MAXT), 256, SMEM_G2>>>(rb2);
    combine_kernel<<<Tt, 256>>>(out);
}

// round 7
// speedup vs baseline: 11.1588x; 1.3196x over previous
#include <cuda_runtime.h>
#include <cuda_fp16.h>
#include <stdint.h>

#define Tt 8192
#define Dd 1024
#define Ff 4096
#define Oo 1024
#define Ee 4
#define NSs 2
#define N1 24576
#define HN 8192
#define MAXT 132
#define RPAD (MAXT * 128)

#define BM 128
#define BN 128
#define BKC 64
#define TILEB (128 * 128)

// single-operand pipeline: 2 tiles/stage, 5 stages
#define STG 5
#define STAGEB (2 * TILEB)
#define SMEM_G (STG * STAGEB)        // 163840

// ---------------- device scratch (allocation-free) ----------------
__device__ __align__(256) __half g_X[(size_t)Tt * Dd];
__device__ __align__(256) __half g_W1[(size_t)N1 * Dd];    // [n][k]
__device__ __align__(256) __half g_W2[(size_t)Oo * N1];    // [o][c]
__device__ __align__(256) __half g_Hsh[(size_t)Tt * HN];   // shared hidden
__device__ __align__(256) __half g_R[(size_t)RPAD * Ff];   // routed hidden (gathered)
__device__ __align__(256) float g_Rout[(size_t)RPAD * Oo];
__device__ float2 g_tw[Tt];
__device__ int2   g_ti[Tt];
__device__ int2   g_pp[Tt];
__device__ int    g_rows[RPAD];
__device__ int    g_cnt[Ee];
__device__ int    g_fill[Ee];
__device__ int    g_off[Ee];
__device__ int    g_tile_e[MAXT];
__device__ int    g_tile_m0[MAXT];

// ---------------- helpers ----------------
__device__ __forceinline__ uint32_t smem_u32(const void* p) {
    return (uint32_t)__cvta_generic_to_shared(p);
}
__device__ __forceinline__ uint32_t sw128(uint32_t x) { return x ^ ((x >> 3) & 0x70u); }

__device__ __forceinline__ void cp16(uint32_t s, const void* g) {
    asm volatile("cp.async.cg.shared.global [%0], [%1], 16;\n" :: "r"(s), "l"(g));
}
__device__ __forceinline__ void cp_commit() { asm volatile("cp.async.commit_group;\n"); }
template <int N> __device__ __forceinline__ void cp_wait() {
    asm volatile("cp.async.wait_group %0;\n" :: "n"(N));
}
__device__ __forceinline__ void ldsm_x4(uint32_t* r, uint32_t addr) {
    asm volatile("ldmatrix.sync.aligned.m8n8.x4.shared.b16 {%0,%1,%2,%3}, [%4];"
                 : "=r"(r[0]), "=r"(r[1]), "=r"(r[2]), "=r"(r[3]) : "r"(addr));
}
__device__ __forceinline__ void mma16816(float* d, const uint32_t* a, const uint32_t* b) {
    asm volatile(
        "mma.sync.aligned.m16n8k16.row.col.f32.f16.f16.f32 "
        "{%0,%1,%2,%3}, {%4,%5,%6,%7}, {%8,%9}, {%0,%1,%2,%3};"
        : "+f"(d[0]), "+f"(d[1]), "+f"(d[2]), "+f"(d[3])
        : "r"(a[0]), "r"(a[1]), "r"(a[2]), "r"(a[3]), "r"(b[0]), "r"(b[1]));
}

// ---------------- routing setup ----------------
__global__ void init_kernel() {
    if (threadIdx.x < Ee) { g_cnt[threadIdx.x] = 0; g_fill[threadIdx.x] = 0; }
}

__global__ void gate_kernel(const float* __restrict__ x,
                            const float* __restrict__ gw,
                            const float* __restrict__ gb) {
    int t = blockIdx.x * (blockDim.x >> 5) + (threadIdx.x >> 5);
    int lane = threadIdx.x & 31;
    if (t >= Tt) return;
    float a0 = 0.f, a1 = 0.f, a2 = 0.f, a3 = 0.f;
    const float* xr = x + (size_t)t * Dd;
    for (int d = lane; d < Dd; d += 32) {
        float xv = xr[d];
        a0 += xv * gw[d * Ee + 0]; a1 += xv * gw[d * Ee + 1];
        a2 += xv * gw[d * Ee + 2]; a3 += xv * gw[d * Ee + 3];
    }
    #pragma unroll
    for (int off = 16; off; off >>= 1) {
        a0 += __shfl_xor_sync(~0u, a0, off); a1 += __shfl_xor_sync(~0u, a1, off);
        a2 += __shfl_xor_sync(~0u, a2, off); a3 += __shfl_xor_sync(~0u, a3, off);
    }
    if (lane == 0) {
        float lg[Ee] = {a0 + gb[0], a1 + gb[1], a2 + gb[2], a3 + gb[3]};
        float mx = fmaxf(fmaxf(lg[0], lg[1]), fmaxf(lg[2], lg[3]));
        float w[Ee]; float s = 0.f;
        #pragma unroll
        for (int e = 0; e < Ee; e++) { w[e] = __expf(lg[e] - mx); s += w[e]; }
        float inv = 1.f / s;
        #pragma unroll
        for (int e = 0; e < Ee; e++) w[e] *= inv;
        int i1 = 0;
        #pragma unroll
        for (int e = 1; e < Ee; e++) if (w[e] > w[i1]) i1 = e;
        int i2 = -1;
        #pragma unroll
        for (int e = 0; e < Ee; e++) {
            if (e == i1) continue;
            if (i2 < 0 || w[e] > w[i2]) i2 = e;
        }
        g_tw[t] = make_float2(w[i1], w[i2]);
        g_ti[t] = make_int2(i1, i2);
        atomicAdd(&g_cnt[i1], 1);
        atomicAdd(&g_cnt[i2], 1);
    }
}

__global__ void setup_kernel() {
    __shared__ int soff[Ee], snt[Ee];
    if (threadIdx.x == 0) {
        int o = 0, tt = 0;
        for (int e = 0; e < Ee; e++) {
            soff[e] = o;
            snt[e] = (g_cnt[e] + 127) >> 7;
            o += snt[e] << 7;
            g_off[e] = soff[e];
        }
        for (int e = 0; e < Ee; e++)
            for (int i = 0; i < snt[e]; i++) {
                g_tile_e[tt] = e;
                g_tile_m0[tt] = soff[e] + (i << 7);
                tt++;
            }
        for (; tt < MAXT; tt++) g_tile_e[tt] = -1;
    }
    __syncthreads();
    for (int e = 0; e < Ee; e++) {
        int base = soff[e], c = g_cnt[e], end = snt[e] << 7;
        for (int i = c + threadIdx.x; i < end; i += blockDim.x) g_rows[base + i] = 0;
    }
}

__global__ void scatter_kernel() {
    int t = blockIdx.x * blockDim.x + threadIdx.x;
    if (t >= Tt) return;
    int2 ii = g_ti[t];
    int p = atomicAdd(&g_fill[ii.x], 1);
    int idx1 = g_off[ii.x] + p;
    g_rows[idx1] = t;
    p = atomicAdd(&g_fill[ii.y], 1);
    int idx2 = g_off[ii.y] + p;
    g_rows[idx2] = t;
    g_pp[t] = make_int2(idx1, idx2);
}

// ---------------- conversions ----------------
__global__ void cvt_x(const float* __restrict__ x) {
    int i = blockIdx.x * blockDim.x + threadIdx.x;
    g_X[i] = __float2half_rn(x[i]);
}

__global__ void cvt_w1(const float* __restrict__ sw1, const float* __restrict__ rw1) {
    __shared__ float t[32][33];
    int nb = blockIdx.x * 32, kb = blockIdx.y * 32;
    int j = nb >> 12, f0 = nb & (Ff - 1);
    const float* W = (j < NSs) ? sw1 + (size_t)j * Dd * Ff : rw1 + (size_t)(j - NSs) * Dd * Ff;
    for (int i = threadIdx.y; i < 32; i += 8)
        t[i][threadIdx.x] = W[(size_t)(kb + i) * Ff + f0 + threadIdx.x];
    __syncthreads();
    for (int i = threadIdx.y; i < 32; i += 8) {
        int n = nb + i, k = kb + threadIdx.x;
        g_W1[(size_t)n * Dd + k] = __float2half_rn(t[threadIdx.x][i]);
    }
}

__global__ void cvt_w2(const float* __restrict__ sw2, const float* __restrict__ rw2) {
    __shared__ float t[32][33];
    int ob = blockIdx.x * 32, cb = blockIdx.y * 32;
    int j = cb >> 12, f0 = cb & (Ff - 1);
    const float* W = (j < NSs) ? sw2 + (size_t)j * Ff * Oo : rw2 + (size_t)(j - NSs) * Ff * Oo;
    for (int i = threadIdx.y; i < 32; i += 8)
        t[i][threadIdx.x] = W[(size_t)(f0 + i) * Oo + ob + threadIdx.x];
    __syncthreads();
    for (int i = threadIdx.y; i < 32; i += 8) {
        int o = ob + i, c = cb + threadIdx.x;
        g_W2[(size_t)o * N1 + c] = __float2half_rn(t[threadIdx.x][i]);
    }
}

// ---------------- GEMM machinery ----------------
__device__ __forceinline__ void load_tile256(uint32_t sbase, const __half* g,
                                             int4 rows, int k0, int pitch, int tid) {
    int c16 = (tid & 7) * 16;
    uint32_t soff = (uint32_t)((tid >> 3) * 128 + c16);
    cp16(sbase + sw128(soff),             (const char*)g + ((size_t)rows.x * pitch + k0) * 2 + c16);
    cp16(sbase + sw128(soff + 32 * 128),  (const char*)g + ((size_t)rows.y * pitch + k0) * 2 + c16);
    cp16(sbase + sw128(soff + 64 * 128),  (const char*)g + ((size_t)rows.z * pitch + k0) * 2 + c16);
    cp16(sbase + sw128(soff + 96 * 128),  (const char*)g + ((size_t)rows.w * pitch + k0) * 2 + c16);
}

__device__ __forceinline__ void load_stage(uint32_t st,
                                           const __half* A, int pitchA, int4 ar,
                                           const __half* B, int pitchB, int4 br,
                                           int k0, int tid) {
    load_tile256(st + 0 * TILEB, A, ar, k0, pitchA, tid);
    load_tile256(st + 1 * TILEB, B, br, k0, pitchB, tid);
    cp_commit();
}

__device__ __forceinline__ void mainloop(float acc[4][4][4], uint32_t sb,
                                         const __half* A, int pitchA, int4 ar,
                                         const __half* B, int pitchB, int4 br, int K) {
    const int tid = threadIdx.x;
    const int wid = tid >> 5, lane = tid & 31;
    const int wm = wid >> 2, wn = wid & 3;
    const int NC = K / BKC;

    #pragma unroll
    for (int mi = 0; mi < 4; mi++)
        #pragma unroll
        for (int ni = 0; ni < 4; ni++)
            #pragma unroll
            for (int d = 0; d < 4; d++) acc[mi][ni][d] = 0.f;

    #pragma unroll
    for (int s = 0; s < STG - 1; s++)
        load_stage(sb + s * STAGEB, A, pitchA, ar, B, pitchB, br, s * BKC, tid);

    const uint32_t aRow = (uint32_t)(wm * 64 + (lane & 15));
    const uint32_t aKb  = (uint32_t)(((lane >> 4) & 1) << 4);
    const uint32_t bRow = (uint32_t)(wn * 32 + (lane & 7) + (((lane >> 4) & 1) << 3));
    const uint32_t bKb  = (uint32_t)(((lane >> 3) & 1) << 4);

    for (int c = 0; c < NC; c++) {
        uint32_t st = sb + (c - (c / STG) * STG) * STAGEB;
        cp_wait<STG - 2>();
        __syncthreads();
        {
            int cn = c + STG - 1;
            if (cn < NC)
                load_stage(sb + (cn - (cn / STG) * STG) * STAGEB,
                           A, pitchA, ar, B, pitchB, br, cn * BKC, tid);
        }

        #pragma unroll
        for (int ks = 0; ks < 4; ks++) {
            const uint32_t kb = (uint32_t)(ks * 32);
            uint32_t af[4][4];
            uint32_t bf[4][2];
            #pragma unroll
            for (int mi = 0; mi < 4; mi++)
                ldsm_x4(af[mi], st + 0 * TILEB + sw128((aRow + mi * 16) * 128 + kb + aKb));
            #pragma unroll
            for (int n2 = 0; n2 < 2; n2++) {
                uint32_t r[4];
                ldsm_x4(r, st + 1 * TILEB + sw128((bRow + n2 * 16) * 128 + kb + bKb));
                bf[n2 * 2][0] = r[0]; bf[n2 * 2][1] = r[1];
                bf[n2 * 2 + 1][0] = r[2]; bf[n2 * 2 + 1][1] = r[3];
            }
            #pragma unroll
            for (int mi = 0; mi < 4; mi++)
                #pragma unroll
                for (int ni = 0; ni < 4; ni++)
                    mma16816(acc[mi][ni], af[mi], bf[ni]);
        }
    }
}

__device__ __forceinline__ int4 seq_rows(int base, int tid) {
    int r = base + (tid >> 3);
    return make_int4(r, r + 32, r + 64, r + 96);
}

// ---------------- GEMM1 shared: H_sh = 0.5 * relu(X @ W1_sh + sb1) ----------------
__global__ __launch_bounds__(256, 1)
void gemm1_sh(const float* __restrict__ sb1) {
    extern __shared__ __align__(1024) char smem[];
    uint32_t sb = smem_u32(smem);
    const int m0 = blockIdx.x * BM;
    const int n0 = blockIdx.y * BN;
    const int tid = threadIdx.x;

    float acc[4][4][4];
    mainloop(acc, sb, g_X, Dd, seq_rows(m0, tid), g_W1, Dd, seq_rows(n0, tid), Dd);

    const int wid = tid >> 5, lane = tid & 31;
    const int wm = wid >> 2, wn = wid & 3;
    const int j = n0 >> 12, f0 = n0 & (Ff - 1);
    const float* bb = sb1 + j * Ff;

    #pragma unroll
    for (int mi = 0; mi < 4; mi++)
        #pragma unroll
        for (int h = 0; h < 2; h++) {
            const int row = m0 + wm * 64 + mi * 16 + (lane >> 2) + h * 8;
            #pragma unroll
            for (int ni = 0; ni < 4; ni++) {
                const int col = wn * 32 + ni * 8 + (lane & 3) * 2;
                float v0 = fmaxf(acc[mi][ni][h * 2 + 0] + bb[f0 + col], 0.f) * 0.5f;
                float v1 = fmaxf(acc[mi][ni][h * 2 + 1] + bb[f0 + col + 1], 0.f) * 0.5f;
                __half2 hv;
                hv.x = __float2half_rn(v0);
                hv.y = __float2half_rn(v1);
                *(__half2*)(g_Hsh + (size_t)row * HN + n0 + col) = hv;
            }
        }
}

// ---------------- GEMM1 routed: R = relu(X[g] @ W1_e + rb1_e) ----------------
__global__ __launch_bounds__(256, 1)
void gemm1_rt(const float* __restrict__ rb1) {
    const int bm = blockIdx.x;
    const int e = g_tile_e[bm];
    if (e < 0) return;
    extern __shared__ __align__(1024) char smem[];
    uint32_t sb = smem_u32(smem);
    const int m0 = g_tile_m0[bm];
    const int n0 = blockIdx.y * BN;
    const int tid = threadIdx.x;

    int rb = m0 + (tid >> 3);
    int4 ar = make_int4(g_rows[rb], g_rows[rb + 32], g_rows[rb + 64], g_rows[rb + 96]);
    const __half* W = g_W1 + (size_t)(NSs + e) * Ff * Dd;

    float acc[4][4][4];
    mainloop(acc, sb, g_X, Dd, ar, W, Dd, seq_rows(n0, tid), Dd);

    const int wid = tid >> 5, lane = tid & 31;
    const int wm = wid >> 2, wn = wid & 3;
    const float* bb = rb1 + e * Ff + n0;

    #pragma unroll
    for (int mi = 0; mi < 4; mi++)
        #pragma unroll
        for (int h = 0; h < 2; h++) {
            const int row = m0 + wm * 64 + mi * 16 + (lane >> 2) + h * 8;
            #pragma unroll
            for (int ni = 0; ni < 4; ni++) {
                const int col = wn * 32 + ni * 8 + (lane & 3) * 2;
                float v0 = fmaxf(acc[mi][ni][h * 2 + 0] + bb[col], 0.f);
                float v1 = fmaxf(acc[mi][ni][h * 2 + 1] + bb[col + 1], 0.f);
                __half2 hv;
                hv.x = __float2half_rn(v0);
                hv.y = __float2half_rn(v1);
                *(__half2*)(g_R + (size_t)row * Ff + n0 + col) = hv;
            }
        }
}

// ---------------- GEMM2 shared: out = H_sh @ W2_sh + 0.5*(sb2_0+sb2_1) ----------------
__global__ __launch_bounds__(256, 1)
void gemm2_sh(const float* __restrict__ sb2, float* __restrict__ out) {
    extern __shared__ __align__(1024) char smem[];
    uint32_t sb = smem_u32(smem);
    const int n0 = blockIdx.x * BN;
    const int m0 = blockIdx.y * BM;
    const int tid = threadIdx.x;

    float acc[4][4][4];
    mainloop(acc, sb, g_Hsh, HN, seq_rows(m0, tid), g_W2, N1, seq_rows(n0, tid), HN);

    const int wid = tid >> 5, lane = tid & 31;
    const int wm = wid >> 2, wn = wid & 3;

    #pragma unroll
    for (int mi = 0; mi < 4; mi++)
        #pragma unroll
        for (int h = 0; h < 2; h++) {
            const int row = m0 + wm * 64 + mi * 16 + (lane >> 2) + h * 8;
            #pragma unroll
            for (int ni = 0; ni < 4; ni++) {
                const int col = n0 + wn * 32 + ni * 8 + (lane & 3) * 2;
                float2 v;
                v.x = acc[mi][ni][h * 2 + 0] + 0.5f * (sb2[col] + sb2[Oo + col]);
                v.y = acc[mi][ni][h * 2 + 1] + 0.5f * (sb2[col + 1] + sb2[Oo + col + 1]);
                *(float2*)(out + (size_t)row * Oo + col) = v;
            }
        }
}

// ---------------- GEMM2 routed: Rout = R @ W2_e + rb2_e ----------------
__global__ __launch_bounds__(256, 1)
void gemm2_rt(const float* __restrict__ rb2) {
    const int bm = blockIdx.y;
    const int e = g_tile_e[bm];
    if (e < 0) return;
    extern __shared__ __align__(1024) char smem[];
    uint32_t sb = smem_u32(smem);
    const int m0 = g_tile_m0[bm];
    const int n0 = blockIdx.x * BN;
    const int tid = threadIdx.x;

    const __half* W = g_W2 + (size_t)(NSs + e) * Ff;

    float acc[4][4][4];
    mainloop(acc, sb, g_R, Ff, seq_rows(m0, tid), W, N1, seq_rows(n0, tid), Ff);

    const int wid = tid >> 5, lane = tid & 31;
    const int wm = wid >> 2, wn = wid & 3;

    #pragma unroll
    for (int mi = 0; mi < 4; mi++)
        #pragma unroll
        for (int h = 0; h < 2; h++) {
            const int row = m0 + wm * 64 + mi * 16 + (lane >> 2) + h * 8;
            #pragma unroll
            for (int ni = 0; ni < 4; ni++) {
                const int col = n0 + wn * 32 + ni * 8 + (lane & 3) * 2;
                float2 v;
                v.x = acc[mi][ni][h * 2 + 0] + rb2[e * Oo + col];
                v.y = acc[mi][ni][h * 2 + 1] + rb2[e * Oo + col + 1];
                *(float2*)(g_Rout + (size_t)row * Oo + col) = v;
            }
        }
}

// ---------------- combine ----------------
__global__ void combine_kernel(float* __restrict__ out) {
    int t = blockIdx.x;
    int o = threadIdx.x * 4;
    float2 w = g_tw[t];
    int2 p = g_pp[t];
    float4 a  = *(const float4*)(out + (size_t)t * Oo + o);
    float4 r1 = *(const float4*)(g_Rout + (size_t)p.x * Oo + o);
    float4 r2 = *(const float4*)(g_Rout + (size_t)p.y * Oo + o);
    a.x += w.x * r1.x + w.y * r2.x;
    a.y += w.x * r1.y + w.y * r2.y;
    a.z += w.x * r1.z + w.y * r2.z;
    a.w += w.x * r1.w + w.y * r2.w;
    *(float4*)(out + (size_t)t * Oo + o) = a;
}

// ---------------- launch ----------------
extern "C" void kernel_launch(void* const* d_in, const int* in_sizes, int n_in,
                              void* d_out, int out_size) {
    const float* x      = (const float*)d_in[0];
    const float* gate_w = (const float*)d_in[1];
    const float* gate_b = (const float*)d_in[2];
    const float* sw1    = (const float*)d_in[3];
    const float* sb1    = (const float*)d_in[4];
    const float* sw2    = (const float*)d_in[5];
    const float* sb2    = (const float*)d_in[6];
    const float* rw1    = (const float*)d_in[7];
    const float* rb1    = (const float*)d_in[8];
    const float* rw2    = (const float*)d_in[9];
    const float* rb2    = (const float*)d_in[10];
    float* out = (float*)d_out;

    cudaFuncSetAttribute(gemm1_sh, cudaFuncAttributeMaxDynamicSharedMemorySize, SMEM_G);
    cudaFuncSetAttribute(gemm1_rt, cudaFuncAttributeMaxDynamicSharedMemorySize, SMEM_G);
    cudaFuncSetAttribute(gemm2_sh, cudaFuncAttributeMaxDynamicSharedMemorySize, SMEM_G);
    cudaFuncSetAttribute(gemm2_rt, cudaFuncAttributeMaxDynamicSharedMemorySize, SMEM_G);

    init_kernel<<<1, 32>>>();
    gate_kernel<<<Tt / 8, 256>>>(x, gate_w, gate_b);
    setup_kernel<<<1, 256>>>();
    scatter_kernel<<<Tt / 256, 256>>>();

    cvt_x<<<(Tt * Dd) / 256, 256>>>(x);
    dim3 bt(32, 8);
    cvt_w1<<<dim3(N1 / 32, Dd / 32), bt>>>(sw1, rw1);
    cvt_w2<<<dim3(Oo / 32, N1 / 32), bt>>>(sw2, rw2);

    gemm1_sh<<<dim3(Tt / BM, HN / BN), 256, SMEM_G>>>(sb1);
    gemm1_rt<<<dim3(MAXT, Ff / BN), 256, SMEM_G>>>(rb1);
    gemm2_sh<<<dim3(Oo / BN, Tt / BM), 256, SMEM_G>>>(sb2, out);
    gemm2_rt<<<dim3(Oo / BN, MAXT), 256, SMEM_G>>>(rb2);
    combine_kernel<<<Tt, 256>>>(out);
}

// round 8
// speedup vs baseline: 12.3992x; 1.1112x over previous
#include <cuda_runtime.h>
#include <cuda_fp16.h>
#include <stdint.h>

#define Tt 8192
#define Dd 1024
#define Ff 4096
#define Oo 1024
#define Ee 4
#define NSs 2
#define N1 24576
#define HN 8192
#define MAXT 132
#define RPAD (MAXT * 128)

#define BM 128
#define BN 256
#define BKC 64
#define TILEA (128 * 128)            // 16 KB
#define TILEBB (256 * 128)           // 32 KB
#define STG 4
#define STAGEB (TILEA + TILEBB)      // 48 KB
#define SMEM_G (STG * STAGEB)        // 196608

// ---------------- device scratch (allocation-free) ----------------
__device__ __align__(256) __half g_X[(size_t)Tt * Dd];
__device__ __align__(256) __half g_W1[(size_t)N1 * Dd];    // [n][k]
__device__ __align__(256) __half g_W2[(size_t)Oo * N1];    // [o][c]
__device__ __align__(256) __half g_Hsh[(size_t)Tt * HN];   // shared hidden
__device__ __align__(256) __half g_R[(size_t)RPAD * Ff];   // routed hidden (gathered)
__device__ __align__(256) float g_Rout[(size_t)RPAD * Oo];
__device__ float2 g_tw[Tt];
__device__ int2   g_ti[Tt];
__device__ int2   g_pp[Tt];
__device__ int    g_rows[RPAD];
__device__ int    g_cnt[Ee];
__device__ int    g_fill[Ee];
__device__ int    g_off[Ee];
__device__ int    g_tile_e[MAXT];
__device__ int    g_tile_m0[MAXT];

// ---------------- helpers ----------------
__device__ __forceinline__ uint32_t smem_u32(const void* p) {
    return (uint32_t)__cvta_generic_to_shared(p);
}
__device__ __forceinline__ uint32_t sw128(uint32_t x) { return x ^ ((x >> 3) & 0x70u); }

__device__ __forceinline__ void cp16(uint32_t s, const void* g) {
    asm volatile("cp.async.cg.shared.global [%0], [%1], 16;\n" :: "r"(s), "l"(g));
}
__device__ __forceinline__ void cp_commit() { asm volatile("cp.async.commit_group;\n"); }
template <int N> __device__ __forceinline__ void cp_wait() {
    asm volatile("cp.async.wait_group %0;\n" :: "n"(N));
}
__device__ __forceinline__ void ldsm_x4(uint32_t* r, uint32_t addr) {
    asm volatile("ldmatrix.sync.aligned.m8n8.x4.shared.b16 {%0,%1,%2,%3}, [%4];"
                 : "=r"(r[0]), "=r"(r[1]), "=r"(r[2]), "=r"(r[3]) : "r"(addr));
}
__device__ __forceinline__ void mma16816(float* d, const uint32_t* a, const uint32_t* b) {
    asm volatile(
        "mma.sync.aligned.m16n8k16.row.col.f32.f16.f16.f32 "
        "{%0,%1,%2,%3}, {%4,%5,%6,%7}, {%8,%9}, {%0,%1,%2,%3};"
        : "+f"(d[0]), "+f"(d[1]), "+f"(d[2]), "+f"(d[3])
        : "r"(a[0]), "r"(a[1]), "r"(a[2]), "r"(a[3]), "r"(b[0]), "r"(b[1]));
}

// ---------------- routing setup ----------------
__global__ void init_kernel() {
    if (threadIdx.x < Ee) { g_cnt[threadIdx.x] = 0; g_fill[threadIdx.x] = 0; }
}

__global__ void gate_kernel(const float* __restrict__ x,
                            const float* __restrict__ gw,
                            const float* __restrict__ gb) {
    int t = blockIdx.x * (blockDim.x >> 5) + (threadIdx.x >> 5);
    int lane = threadIdx.x & 31;
    if (t >= Tt) return;
    float a0 = 0.f, a1 = 0.f, a2 = 0.f, a3 = 0.f;
    const float* xr = x + (size_t)t * Dd;
    for (int d = lane; d < Dd; d += 32) {
        float xv = xr[d];
        a0 += xv * gw[d * Ee + 0]; a1 += xv * gw[d * Ee + 1];
        a2 += xv * gw[d * Ee + 2]; a3 += xv * gw[d * Ee + 3];
    }
    #pragma unroll
    for (int off = 16; off; off >>= 1) {
        a0 += __shfl_xor_sync(~0u, a0, off); a1 += __shfl_xor_sync(~0u, a1, off);
        a2 += __shfl_xor_sync(~0u, a2, off); a3 += __shfl_xor_sync(~0u, a3, off);
    }
    if (lane == 0) {
        float lg[Ee] = {a0 + gb[0], a1 + gb[1], a2 + gb[2], a3 + gb[3]};
        float mx = fmaxf(fmaxf(lg[0], lg[1]), fmaxf(lg[2], lg[3]));
        float w[Ee]; float s = 0.f;
        #pragma unroll
        for (int e = 0; e < Ee; e++) { w[e] = __expf(lg[e] - mx); s += w[e]; }
        float inv = 1.f / s;
        #pragma unroll
        for (int e = 0; e < Ee; e++) w[e] *= inv;
        int i1 = 0;
        #pragma unroll
        for (int e = 1; e < Ee; e++) if (w[e] > w[i1]) i1 = e;
        int i2 = -1;
        #pragma unroll
        for (int e = 0; e < Ee; e++) {
            if (e == i1) continue;
            if (i2 < 0 || w[e] > w[i2]) i2 = e;
        }
        g_tw[t] = make_float2(w[i1], w[i2]);
        g_ti[t] = make_int2(i1, i2);
        atomicAdd(&g_cnt[i1], 1);
        atomicAdd(&g_cnt[i2], 1);
    }
}

__global__ void setup_kernel() {
    __shared__ int soff[Ee], snt[Ee];
    if (threadIdx.x == 0) {
        int o = 0, tt = 0;
        for (int e = 0; e < Ee; e++) {
            soff[e] = o;
            snt[e] = (g_cnt[e] + 127) >> 7;
            o += snt[e] << 7;
            g_off[e] = soff[e];
        }
        for (int e = 0; e < Ee; e++)
            for (int i = 0; i < snt[e]; i++) {
                g_tile_e[tt] = e;
                g_tile_m0[tt] = soff[e] + (i << 7);
                tt++;
            }
        for (; tt < MAXT; tt++) g_tile_e[tt] = -1;
    }
    __syncthreads();
    for (int e = 0; e < Ee; e++) {
        int base = soff[e], c = g_cnt[e], end = snt[e] << 7;
        for (int i = c + threadIdx.x; i < end; i += blockDim.x) g_rows[base + i] = 0;
    }
}

__global__ void scatter_kernel() {
    int t = blockIdx.x * blockDim.x + threadIdx.x;
    if (t >= Tt) return;
    int2 ii = g_ti[t];
    int p = atomicAdd(&g_fill[ii.x], 1);
    int idx1 = g_off[ii.x] + p;
    g_rows[idx1] = t;
    p = atomicAdd(&g_fill[ii.y], 1);
    int idx2 = g_off[ii.y] + p;
    g_rows[idx2] = t;
    g_pp[t] = make_int2(idx1, idx2);
}

// ---------------- conversions ----------------
__global__ void cvt_x(const float* __restrict__ x) {
    int i = blockIdx.x * blockDim.x + threadIdx.x;
    g_X[i] = __float2half_rn(x[i]);
}

__global__ void cvt_w1(const float* __restrict__ sw1, const float* __restrict__ rw1) {
    __shared__ float t[32][33];
    int nb = blockIdx.x * 32, kb = blockIdx.y * 32;
    int j = nb >> 12, f0 = nb & (Ff - 1);
    const float* W = (j < NSs) ? sw1 + (size_t)j * Dd * Ff : rw1 + (size_t)(j - NSs) * Dd * Ff;
    for (int i = threadIdx.y; i < 32; i += 8)
        t[i][threadIdx.x] = W[(size_t)(kb + i) * Ff + f0 + threadIdx.x];
    __syncthreads();
    for (int i = threadIdx.y; i < 32; i += 8) {
        int n = nb + i, k = kb + threadIdx.x;
        g_W1[(size_t)n * Dd + k] = __float2half_rn(t[threadIdx.x][i]);
    }
}

__global__ void cvt_w2(const float* __restrict__ sw2, const float* __restrict__ rw2) {
    __shared__ float t[32][33];
    int ob = blockIdx.x * 32, cb = blockIdx.y * 32;
    int j = cb >> 12, f0 = cb & (Ff - 1);
    const float* W = (j < NSs) ? sw2 + (size_t)j * Ff * Oo : rw2 + (size_t)(j - NSs) * Ff * Oo;
    for (int i = threadIdx.y; i < 32; i += 8)
        t[i][threadIdx.x] = W[(size_t)(f0 + i) * Oo + ob + threadIdx.x];
    __syncthreads();
    for (int i = threadIdx.y; i < 32; i += 8) {
        int o = ob + i, c = cb + threadIdx.x;
        g_W2[(size_t)o * N1 + c] = __float2half_rn(t[threadIdx.x][i]);
    }
}

// ---------------- GEMM machinery ----------------
// A tile: 128 rows (gatherable via int4 row ids)
__device__ __forceinline__ void load_tileA(uint32_t sbase, const __half* g,
                                           int4 rows, int k0, int pitch, int tid) {
    int c16 = (tid & 7) * 16;
    uint32_t soff = (uint32_t)((tid >> 3) * 128 + c16);
    cp16(sbase + sw128(soff),             (const char*)g + ((size_t)rows.x * pitch + k0) * 2 + c16);
    cp16(sbase + sw128(soff + 32 * 128),  (const char*)g + ((size_t)rows.y * pitch + k0) * 2 + c16);
    cp16(sbase + sw128(soff + 64 * 128),  (const char*)g + ((size_t)rows.z * pitch + k0) * 2 + c16);
    cp16(sbase + sw128(soff + 96 * 128),  (const char*)g + ((size_t)rows.w * pitch + k0) * 2 + c16);
}

// B tile: 256 sequential rows
__device__ __forceinline__ void load_tileB(uint32_t sbase, const __half* g,
                                           int row0, int k0, int pitch, int tid) {
    int c16 = (tid & 7) * 16;
    int r = row0 + (tid >> 3);
    uint32_t soff = (uint32_t)((tid >> 3) * 128 + c16);
    const char* gp = (const char*)g + ((size_t)r * pitch + k0) * 2 + c16;
    size_t gstep = (size_t)32 * pitch * 2;
    #pragma unroll
    for (int rr = 0; rr < 8; rr++) {
        cp16(sbase + sw128(soff + rr * 32 * 128), gp);
        gp += gstep;
    }
}

__device__ __forceinline__ void load_stage(uint32_t st,
                                           const __half* A, int pitchA, int4 ar,
                                           const __half* B, int pitchB, int bn0,
                                           int k0, int tid) {
    load_tileA(st, A, ar, k0, pitchA, tid);
    load_tileB(st + TILEA, B, bn0, k0, pitchB, tid);
    cp_commit();
}

// warp tile 64x64: 8 warps as 2(m) x 4(n) over 128x256 CTA tile
__device__ __forceinline__ void mainloop(float acc[4][8][4], uint32_t sb,
                                         const __half* A, int pitchA, int4 ar,
                                         const __half* B, int pitchB, int bn0, int K) {
    const int tid = threadIdx.x;
    const int wid = tid >> 5, lane = tid & 31;
    const int wm = wid >> 2, wn = wid & 3;
    const int NC = K / BKC;

    #pragma unroll
    for (int mi = 0; mi < 4; mi++)
        #pragma unroll
        for (int ni = 0; ni < 8; ni++)
            #pragma unroll
            for (int d = 0; d < 4; d++) acc[mi][ni][d] = 0.f;

    #pragma unroll
    for (int s = 0; s < STG - 1; s++)
        load_stage(sb + s * STAGEB, A, pitchA, ar, B, pitchB, bn0, s * BKC, tid);

    const uint32_t aRow = (uint32_t)(wm * 64 + (lane & 15));
    const uint32_t aKb  = (uint32_t)(((lane >> 4) & 1) << 4);
    const uint32_t bRow = (uint32_t)(wn * 64 + (lane & 7) + (((lane >> 4) & 1) << 3));
    const uint32_t bKb  = (uint32_t)(((lane >> 3) & 1) << 4);

    for (int c = 0; c < NC; c++) {
        uint32_t st = sb + (c - (c / STG) * STG) * STAGEB;
        cp_wait<STG - 2>();
        __syncthreads();
        {
            int cn = c + STG - 1;
            if (cn < NC)
                load_stage(sb + (cn - (cn / STG) * STG) * STAGEB,
                           A, pitchA, ar, B, pitchB, bn0, cn * BKC, tid);
        }

        #pragma unroll
        for (int ks = 0; ks < 4; ks++) {
            const uint32_t kb = (uint32_t)(ks * 32);
            uint32_t af[4][4];
            uint32_t bf[8][2];
            #pragma unroll
            for (int mi = 0; mi < 4; mi++)
                ldsm_x4(af[mi], st + sw128((aRow + mi * 16) * 128 + kb + aKb));
            #pragma unroll
            for (int n2 = 0; n2 < 4; n2++) {
                uint32_t r[4];
                ldsm_x4(r, st + TILEA + sw128((bRow + n2 * 16) * 128 + kb + bKb));
                bf[n2 * 2][0] = r[0]; bf[n2 * 2][1] = r[1];
                bf[n2 * 2 + 1][0] = r[2]; bf[n2 * 2 + 1][1] = r[3];
            }
            #pragma unroll
            for (int mi = 0; mi < 4; mi++)
                #pragma unroll
                for (int ni = 0; ni < 8; ni++)
                    mma16816(acc[mi][ni], af[mi], bf[ni]);
        }
    }
}

__device__ __forceinline__ int4 seq_rows(int base, int tid) {
    int r = base + (tid >> 3);
    return make_int4(r, r + 32, r + 64, r + 96);
}

// ---------------- GEMM1 shared: H_sh = 0.5 * relu(X @ W1_sh + sb1) ----------------
__global__ __launch_bounds__(256, 1)
void gemm1_sh(const float* __restrict__ sb1) {
    extern __shared__ __align__(1024) char smem[];
    uint32_t sb = smem_u32(smem);
    const int m0 = blockIdx.x * BM;
    const int n0 = blockIdx.y * BN;
    const int tid = threadIdx.x;

    float acc[4][8][4];
    mainloop(acc, sb, g_X, Dd, seq_rows(m0, tid), g_W1, Dd, n0, Dd);

    const int wid = tid >> 5, lane = tid & 31;
    const int wm = wid >> 2, wn = wid & 3;
    const int j = n0 >> 12, f0 = n0 & (Ff - 1);
    const float* bb = sb1 + j * Ff;

    #pragma unroll
    for (int mi = 0; mi < 4; mi++)
        #pragma unroll
        for (int h = 0; h < 2; h++) {
            const int row = m0 + wm * 64 + mi * 16 + (lane >> 2) + h * 8;
            #pragma unroll
            for (int ni = 0; ni < 8; ni++) {
                const int col = wn * 64 + ni * 8 + (lane & 3) * 2;
                float v0 = fmaxf(acc[mi][ni][h * 2 + 0] + bb[f0 + col], 0.f) * 0.5f;
                float v1 = fmaxf(acc[mi][ni][h * 2 + 1] + bb[f0 + col + 1], 0.f) * 0.5f;
                __half2 hv;
                hv.x = __float2half_rn(v0);
                hv.y = __float2half_rn(v1);
                *(__half2*)(g_Hsh + (size_t)row * HN + n0 + col) = hv;
            }
        }
}

// ---------------- GEMM1 routed: R = relu(X[g] @ W1_e + rb1_e) ----------------
__global__ __launch_bounds__(256, 1)
void gemm1_rt(const float* __restrict__ rb1) {
    const int bm = blockIdx.x;
    const int e = g_tile_e[bm];
    if (e < 0) return;
    extern __shared__ __align__(1024) char smem[];
    uint32_t sb = smem_u32(smem);
    const int m0 = g_tile_m0[bm];
    const int n0 = blockIdx.y * BN;
    const int tid = threadIdx.x;

    int rb = m0 + (tid >> 3);
    int4 ar = make_int4(g_rows[rb], g_rows[rb + 32], g_rows[rb + 64], g_rows[rb + 96]);
    const __half* W = g_W1 + (size_t)(NSs + e) * Ff * Dd;

    float acc[4][8][4];
    mainloop(acc, sb, g_X, Dd, ar, W, Dd, n0, Dd);

    const int wid = tid >> 5, lane = tid & 31;
    const int wm = wid >> 2, wn = wid & 3;
    const float* bb = rb1 + e * Ff + n0;

    #pragma unroll
    for (int mi = 0; mi < 4; mi++)
        #pragma unroll
        for (int h = 0; h < 2; h++) {
            const int row = m0 + wm * 64 + mi * 16 + (lane >> 2) + h * 8;
            #pragma unroll
            for (int ni = 0; ni < 8; ni++) {
                const int col = wn * 64 + ni * 8 + (lane & 3) * 2;
                float v0 = fmaxf(acc[mi][ni][h * 2 + 0] + bb[col], 0.f);
                float v1 = fmaxf(acc[mi][ni][h * 2 + 1] + bb[col + 1], 0.f);
                __half2 hv;
                hv.x = __float2half_rn(v0);
                hv.y = __float2half_rn(v1);
                *(__half2*)(g_R + (size_t)row * Ff + n0 + col) = hv;
            }
        }
}

// ---------------- GEMM2 shared: out = H_sh @ W2_sh + 0.5*(sb2_0+sb2_1) ----------------
__global__ __launch_bounds__(256, 1)
void gemm2_sh(const float* __restrict__ sb2, float* __restrict__ out) {
    extern __shared__ __align__(1024) char smem[];
    uint32_t sb = smem_u32(smem);
    const int n0 = blockIdx.x * BN;
    const int m0 = blockIdx.y * BM;
    const int tid = threadIdx.x;

    float acc[4][8][4];
    mainloop(acc, sb, g_Hsh, HN, seq_rows(m0, tid), g_W2, N1, n0, HN);

    const int wid = tid >> 5, lane = tid & 31;
    const int wm = wid >> 2, wn = wid & 3;

    #pragma unroll
    for (int mi = 0; mi < 4; mi++)
        #pragma unroll
        for (int h = 0; h < 2; h++) {
            const int row = m0 + wm * 64 + mi * 16 + (lane >> 2) + h * 8;
            #pragma unroll
            for (int ni = 0; ni < 8; ni++) {
                const int col = n0 + wn * 64 + ni * 8 + (lane & 3) * 2;
                float2 v;
                v.x = acc[mi][ni][h * 2 + 0] + 0.5f * (sb2[col] + sb2[Oo + col]);
                v.y = acc[mi][ni][h * 2 + 1] + 0.5f * (sb2[col + 1] + sb2[Oo + col + 1]);
                *(float2*)(out + (size_t)row * Oo + col) = v;
            }
        }
}

// ---------------- GEMM2 routed: Rout = R @ W2_e + rb2_e ----------------
__global__ __launch_bounds__(256, 1)
void gemm2_rt(const float* __restrict__ rb2) {
    const int bm = blockIdx.y;
    const int e = g_tile_e[bm];
    if (e < 0) return;
    extern __shared__ __align__(1024) char smem[];
    uint32_t sb = smem_u32(smem);
    const int m0 = g_tile_m0[bm];
    const int n0 = blockIdx.x * BN;
    const int tid = threadIdx.x;

    const __half* W = g_W2 + (size_t)(NSs + e) * Ff;

    float acc[4][8][4];
    mainloop(acc, sb, g_R, Ff, seq_rows(m0, tid), W, N1, n0, Ff);

    const int wid = tid >> 5, lane = tid & 31;
    const int wm = wid >> 2, wn = wid & 3;

    #pragma unroll
    for (int mi = 0; mi < 4; mi++)
        #pragma unroll
        for (int h = 0; h < 2; h++) {
            const int row = m0 + wm * 64 + mi * 16 + (lane >> 2) + h * 8;
            #pragma unroll
            for (int ni = 0; ni < 8; ni++) {
                const int col = n0 + wn * 64 + ni * 8 + (lane & 3) * 2;
                float2 v;
                v.x = acc[mi][ni][h * 2 + 0] + rb2[e * Oo + col];
                v.y = acc[mi][ni][h * 2 + 1] + rb2[e * Oo + col + 1];
                *(float2*)(g_Rout + (size_t)row * Oo + col) = v;
            }
        }
}

// ---------------- combine ----------------
__global__ void combine_kernel(float* __restrict__ out) {
    int t = blockIdx.x;
    int o = threadIdx.x * 4;
    float2 w = g_tw[t];
    int2 p = g_pp[t];
    float4 a  = *(const float4*)(out + (size_t)t * Oo + o);
    float4 r1 = *(const float4*)(g_Rout + (size_t)p.x * Oo + o);
    float4 r2 = *(const float4*)(g_Rout + (size_t)p.y * Oo + o);
    a.x += w.x * r1.x + w.y * r2.x;
    a.y += w.x * r1.y + w.y * r2.y;
    a.z += w.x * r1.z + w.y * r2.z;
    a.w += w.x * r1.w + w.y * r2.w;
    *(float4*)(out + (size_t)t * Oo + o) = a;
}

// ---------------- launch ----------------
extern "C" void kernel_launch(void* const* d_in, const int* in_sizes, int n_in,
                              void* d_out, int out_size) {
    const float* x      = (const float*)d_in[0];
    const float* gate_w = (const float*)d_in[1];
    const float* gate_b = (const float*)d_in[2];
    const float* sw1    = (const float*)d_in[3];
    const float* sb1    = (const float*)d_in[4];
    const float* sw2    = (const float*)d_in[5];
    const float* sb2    = (const float*)d_in[6];
    const float* rw1    = (const float*)d_in[7];
    const float* rb1    = (const float*)d_in[8];
    const float* rw2    = (const float*)d_in[9];
    const float* rb2    = (const float*)d_in[10];
    float* out = (float*)d_out;

    cudaFuncSetAttribute(gemm1_sh, cudaFuncAttributeMaxDynamicSharedMemorySize, SMEM_G);
    cudaFuncSetAttribute(gemm1_rt, cudaFuncAttributeMaxDynamicSharedMemorySize, SMEM_G);
    cudaFuncSetAttribute(gemm2_sh, cudaFuncAttributeMaxDynamicSharedMemorySize, SMEM_G);
    cudaFuncSetAttribute(gemm2_rt, cudaFuncAttributeMaxDynamicSharedMemorySize, SMEM_G);

    init_kernel<<<1, 32>>>();
    gate_kernel<<<Tt / 8, 256>>>(x, gate_w, gate_b);
    setup_kernel<<<1, 256>>>();
    scatter_kernel<<<Tt / 256, 256>>>();

    cvt_x<<<(Tt * Dd) / 256, 256>>>(x);
    dim3 bt(32, 8);
    cvt_w1<<<dim3(N1 / 32, Dd / 32), bt>>>(sw1, rw1);
    cvt_w2<<<dim3(Oo / 32, N1 / 32), bt>>>(sw2, rw2);

    gemm1_sh<<<dim3(Tt / BM, HN / BN), 256, SMEM_G>>>(sb1);       // 64 x 32
    gemm1_rt<<<dim3(MAXT, Ff / BN), 256, SMEM_G>>>(rb1);          // 132 x 16
    gemm2_sh<<<dim3(Oo / BN, Tt / BM), 256, SMEM_G>>>(sb2, out);  // 4 x 64
    gemm2_rt<<<dim3(Oo / BN, MAXT), 256, SMEM_G>>>(rb2);          // 4 x 132
    combine_kernel<<<Tt, 256>>>(out);
}